// round 1
// baseline (speedup 1.0000x reference)
#include <cuda_runtime.h>
#include <cstdint>

#define NPTS 50000
#define DIM 256

// Scratch (allocation-free rule: static __device__ arrays)
__device__ float g_res[NPTS * DIM];          // residual [N,256]
__device__ float g_a0 [NPTS * (DIM / 4)];    // init MLP out [N,64]
__device__ float g_a1 [NPTS * (DIM / 2)];    // LFA1 out [N,128]
__device__ float g_a2 [NPTS * DIM];          // LFA2 out [N,256]

__device__ __forceinline__ float leaky(float x) {
    return x >= 0.0f ? x : 0.2f * x;
}

// ---------------------------------------------------------------------------
// SGEMM: C[M,Nc] = leaky(A[M,K] @ B[K,Nc] + bias[Nc])  (+ res[M,Nc] if res)
// A row-major [M,K], B row-major [K,Nc] (torch Linear weight as [in,out]).
// BM=128, BN=64, BK=16, 256 threads, 8x4 microtile per thread.
// ---------------------------------------------------------------------------
__global__ __launch_bounds__(256)
void gemm_leaky(const float* __restrict__ A, const float* __restrict__ B,
                const float* __restrict__ bias, const float* __restrict__ res,
                float* __restrict__ C, int M, int Nc, int K)
{
    constexpr int BM = 128, BN = 64, BK = 16;
    __shared__ float As[BK][BM];
    __shared__ float Bs[BK][BN];

    const int t  = threadIdx.x;          // 0..255
    const int tx = t & 15;               // col group
    const int ty = t >> 4;               // row group
    const int rowbase = blockIdx.x * BM;
    const int colbase = blockIdx.y * BN;

    float acc[8][4];
    #pragma unroll
    for (int i = 0; i < 8; i++)
        #pragma unroll
        for (int j = 0; j < 4; j++)
            acc[i][j] = 0.0f;

    for (int kk = 0; kk < K; kk += BK) {
        // --- load A tile (BMxBK = 2048 floats = 512 float4; 2 per thread) ---
        #pragma unroll
        for (int l = 0; l < 2; l++) {
            int e   = t + l * 256;           // 0..511 (float4 units)
            int row = e >> 2;                // 0..127
            int k4  = e & 3;                 // 0..3
            float4 v = make_float4(0.f, 0.f, 0.f, 0.f);
            int grow = rowbase + row;
            if (grow < M)
                v = *reinterpret_cast<const float4*>(
                        A + (size_t)grow * K + kk + k4 * 4);
            As[k4 * 4 + 0][row] = v.x;
            As[k4 * 4 + 1][row] = v.y;
            As[k4 * 4 + 2][row] = v.z;
            As[k4 * 4 + 3][row] = v.w;
        }
        // --- load B tile (BKxBN = 1024 floats = 256 float4; 1 per thread) ---
        {
            int krow = t >> 4;               // 0..15
            int c4   = t & 15;               // 0..15
            float4 v = *reinterpret_cast<const float4*>(
                           B + (size_t)(kk + krow) * Nc + colbase + c4 * 4);
            Bs[krow][c4 * 4 + 0] = v.x;
            Bs[krow][c4 * 4 + 1] = v.y;
            Bs[krow][c4 * 4 + 2] = v.z;
            Bs[krow][c4 * 4 + 3] = v.w;
        }
        __syncthreads();

        #pragma unroll
        for (int k = 0; k < BK; k++) {
            float a[8], b[4];
            #pragma unroll
            for (int i = 0; i < 8; i++) a[i] = As[k][ty + i * 16];
            #pragma unroll
            for (int j = 0; j < 4; j++) b[j] = Bs[k][tx + j * 16];
            #pragma unroll
            for (int i = 0; i < 8; i++)
                #pragma unroll
                for (int j = 0; j < 4; j++)
                    acc[i][j] = fmaf(a[i], b[j], acc[i][j]);
        }
        __syncthreads();
    }

    // --- epilogue: bias + leaky (+ residual) ---
    #pragma unroll
    for (int i = 0; i < 8; i++) {
        int row = rowbase + ty + i * 16;
        if (row >= M) continue;
        #pragma unroll
        for (int j = 0; j < 4; j++) {
            int col = colbase + tx + j * 16;
            float v = leaky(acc[i][j] + bias[col]);
            if (res) v += res[(size_t)row * Nc + col];
            C[(size_t)row * Nc + col] = v;
        }
    }
}

// ---------------------------------------------------------------------------
// LFA: per point n:
//   out[n, 0:D]   = mean_k leaky(geom[n,k,:4] @ Wg[4,D] + bg)
//   out[n, D:2D]  = mean_k feat[idx[n,k], 0:D]
// blockDim = (D, PTS). Gather is coalesced across tx (D*4 bytes per neighbor)
// and the gather source fits in L2 (12.8 / 25.6 MB).
// ---------------------------------------------------------------------------
template <int D, int PTS>
__global__ void lfa_kernel(const float* __restrict__ feat,
                           const float* __restrict__ geom,
                           const int*   __restrict__ idx,
                           const float* __restrict__ wg,
                           const float* __restrict__ bg,
                           float* __restrict__ out, int N)
{
    __shared__ float gs[PTS][16][4];
    __shared__ int   is[PTS][16];

    const int tx = threadIdx.x;      // 0..D-1
    const int ty = threadIdx.y;      // 0..PTS-1
    const int p  = blockIdx.x * PTS + ty;
    const bool valid = (p < N);

    if (valid) {
        if (tx < 64)
            (&gs[ty][0][0])[tx] = geom[(size_t)p * 64 + tx];
        if (tx < 16)
            is[ty][tx] = idx[(size_t)p * 16 + tx];
    }
    __syncthreads();
    if (!valid) return;

    const float w0 = wg[0 * D + tx];
    const float w1 = wg[1 * D + tx];
    const float w2 = wg[2 * D + tx];
    const float w3 = wg[3 * D + tx];
    const float bb = bg[tx];

    float gsum = 0.0f, fsum = 0.0f;
    #pragma unroll
    for (int k = 0; k < 16; k++) {
        float v = fmaf(gs[ty][k][0], w0,
                  fmaf(gs[ty][k][1], w1,
                  fmaf(gs[ty][k][2], w2,
                  fmaf(gs[ty][k][3], w3, bb))));
        gsum += leaky(v);
        fsum += feat[(size_t)is[ty][k] * D + tx];
    }
    out[(size_t)p * (2 * D) + tx]     = gsum * 0.0625f;
    out[(size_t)p * (2 * D) + D + tx] = fsum * 0.0625f;
}

// ---------------------------------------------------------------------------
extern "C" void kernel_launch(void* const* d_in, const int* in_sizes, int n_in,
                              void* d_out, int out_size)
{
    const float* X      = (const float*)d_in[0];   // [N,256]
    const float* geom   = (const float*)d_in[1];   // [N,16,4]
    const int*   idx    = (const int*)  d_in[2];   // [N,16]
    const float* w_res  = (const float*)d_in[3];
    const float* b_res  = (const float*)d_in[4];
    const float* w_init = (const float*)d_in[5];
    const float* b_init = (const float*)d_in[6];
    const float* w_g1   = (const float*)d_in[7];
    const float* b_g1   = (const float*)d_in[8];
    const float* w_g2   = (const float*)d_in[9];
    const float* b_g2   = (const float*)d_in[10];
    const float* w_fin  = (const float*)d_in[11];
    const float* b_fin  = (const float*)d_in[12];
    float* out = (float*)d_out;

    const int N = in_sizes[0] / DIM;  // 50000

    float *resbuf, *a0buf, *a1buf, *a2buf;
    cudaGetSymbolAddress((void**)&resbuf, g_res);
    cudaGetSymbolAddress((void**)&a0buf,  g_a0);
    cudaGetSymbolAddress((void**)&a1buf,  g_a1);
    cudaGetSymbolAddress((void**)&a2buf,  g_a2);

    const int gridM = (N + 127) / 128;

    // 1) residual = leaky(X @ w_res + b_res)   [N,256]
    gemm_leaky<<<dim3(gridM, 4), 256>>>(X, w_res, b_res, nullptr, resbuf,
                                        N, 256, 256);
    // 2) a0 = leaky(X @ w_init + b_init)       [N,64]
    gemm_leaky<<<dim3(gridM, 1), 256>>>(X, w_init, b_init, nullptr, a0buf,
                                        N, 64, 256);
    // 3) a1 = LFA(a0, geom, idx; w_g1)         [N,128]
    lfa_kernel<64, 8><<<(N + 7) / 8, dim3(64, 8)>>>(a0buf, geom, idx,
                                                    w_g1, b_g1, a1buf, N);
    // 4) a2 = LFA(a1, geom, idx; w_g2)         [N,256]
    lfa_kernel<128, 4><<<(N + 3) / 4, dim3(128, 4)>>>(a1buf, geom, idx,
                                                      w_g2, b_g2, a2buf, N);
    // 5) out = leaky(a2 @ w_fin + b_fin) + residual  [N,256]
    gemm_leaky<<<dim3(gridM, 4), 256>>>(a2buf, w_fin, b_fin, resbuf, out,
                                        N, 256, 256);
}

// round 3
// speedup vs baseline: 1.9738x; 1.9738x over previous
#include <cuda_runtime.h>
#include <cstdint>

#define NPTS 50000
#define DIM 256

// ---------------- scratch (no-alloc rule: __device__ globals) --------------
__device__ float g_res[NPTS * DIM];
__device__ float g_a0 [NPTS * (DIM / 4)];
__device__ float g_a1 [NPTS * (DIM / 2)];
__device__ float g_a2 [NPTS * DIM];

__device__ __forceinline__ float leaky(float x) {
    return x >= 0.0f ? x : 0.2f * x;
}

__device__ __forceinline__ uint32_t f2tf32(float f) {
    uint32_t u;
    asm("cvt.rna.tf32.f32 %0, %1;" : "=r"(u) : "f"(f));
    return u;
}

#define MMA_TF32(c, a, b0, b1)                                            \
    asm volatile(                                                         \
        "mma.sync.aligned.m16n8k8.row.col.f32.tf32.tf32.f32 "             \
        "{%0,%1,%2,%3}, {%4,%5,%6,%7}, {%8,%9}, {%0,%1,%2,%3};"           \
        : "+f"((c)[0]), "+f"((c)[1]), "+f"((c)[2]), "+f"((c)[3])          \
        : "r"((a)[0]), "r"((a)[1]), "r"((a)[2]), "r"((a)[3]),             \
          "r"(b0), "r"(b1))

// ---------------------------------------------------------------------------
// tf32 mma.sync GEMM:
//   C[M, NOUT] = leaky(A[M,256] @ B[256,NOUT] + bias)  (+ res if RES)
// CTA tile 128 x CTAN, 8 warps (4 m x 2 n), warp tile 32 x CTAN/2,
// BK=16 (two k8 steps), double-buffered smem, producer cvt to tf32 at STS.
// ---------------------------------------------------------------------------
template <int NOUT, int CTAN, bool RES>
__global__ __launch_bounds__(256, 2)
void mma_gemm(const float* __restrict__ A, const float* __restrict__ B,
              const float* __restrict__ bias, const float* __restrict__ res,
              float* __restrict__ C, int M)
{
    constexpr int KDIM    = 256;
    constexpr int BK      = 16;
    constexpr int NSTAGE  = KDIM / BK;       // 16
    constexpr int ASTRIDE = 20;              // 16 + 4 pad (conflict-free frags)
    constexpr int BSTRIDE = CTAN + 4;
    constexpr int NT8     = CTAN / 16;       // n8 tiles per warp
    constexpr int NBLD    = CTAN / 64;       // B float4 loads per thread
    constexpr int BQ      = CTAN / 4;        // float4 per B k-row

    __shared__ float As[2][128 * ASTRIDE];
    __shared__ float Bs[2][BK * BSTRIDE];

    const int tid = threadIdx.x;
    const int wid = tid >> 5;
    const int lane = tid & 31;
    const int g = lane >> 2;          // groupID
    const int l = lane & 3;           // thread-in-group
    const int warp_m = (wid & 3) * 32;
    const int warp_n = (wid >> 2) * (CTAN / 2);
    const int rowbase = blockIdx.x * 128;
    const int colbase = blockIdx.y * CTAN;

    float c[2][NT8][4];
    #pragma unroll
    for (int mi = 0; mi < 2; mi++)
        #pragma unroll
        for (int ni = 0; ni < NT8; ni++)
            #pragma unroll
            for (int j = 0; j < 4; j++)
                c[mi][ni][j] = 0.0f;

    float4 aR[2], bR[NBLD];

    // ---- LDG for stage t ----
    auto load_stage = [&](int t) {
        const int kk = t * BK;
        #pragma unroll
        for (int i = 0; i < 2; i++) {
            int e = tid + i * 256;          // 0..511
            int r = e >> 2;
            int kq = e & 3;
            int grow = rowbase + r;
            aR[i] = (grow < M)
                ? *reinterpret_cast<const float4*>(
                      A + (size_t)grow * KDIM + kk + kq * 4)
                : make_float4(0.f, 0.f, 0.f, 0.f);
        }
        #pragma unroll
        for (int i = 0; i < NBLD; i++) {
            int e = tid + i * 256;
            int krow = e / BQ;
            int nq = e % BQ;
            bR[i] = *reinterpret_cast<const float4*>(
                B + (size_t)(kk + krow) * NOUT + colbase + nq * 4);
        }
    };

    // ---- cvt + STS into buffer buf ----
    auto store_stage = [&](int buf) {
        #pragma unroll
        for (int i = 0; i < 2; i++) {
            int e = tid + i * 256;
            int r = e >> 2;
            int kq = e & 3;
            float4 v;
            v.x = __uint_as_float(f2tf32(aR[i].x));
            v.y = __uint_as_float(f2tf32(aR[i].y));
            v.z = __uint_as_float(f2tf32(aR[i].z));
            v.w = __uint_as_float(f2tf32(aR[i].w));
            *reinterpret_cast<float4*>(&As[buf][r * ASTRIDE + kq * 4]) = v;
        }
        #pragma unroll
        for (int i = 0; i < NBLD; i++) {
            int e = tid + i * 256;
            int krow = e / BQ;
            int nq = e % BQ;
            float4 v;
            v.x = __uint_as_float(f2tf32(bR[i].x));
            v.y = __uint_as_float(f2tf32(bR[i].y));
            v.z = __uint_as_float(f2tf32(bR[i].z));
            v.w = __uint_as_float(f2tf32(bR[i].w));
            *reinterpret_cast<float4*>(&Bs[buf][krow * BSTRIDE + nq * 4]) = v;
        }
    };

    // ---- prologue ----
    load_stage(0);
    store_stage(0);
    __syncthreads();

    for (int t = 0; t < NSTAGE; t++) {
        const int buf = t & 1;
        if (t + 1 < NSTAGE) load_stage(t + 1);

        const float* as = As[buf];
        const float* bs = Bs[buf];
        #pragma unroll
        for (int k8 = 0; k8 < BK; k8 += 8) {
            uint32_t af[2][4];
            #pragma unroll
            for (int mi = 0; mi < 2; mi++) {
                int r = warp_m + mi * 16 + g;
                af[mi][0] = __float_as_uint(as[r * ASTRIDE + k8 + l]);
                af[mi][1] = __float_as_uint(as[(r + 8) * ASTRIDE + k8 + l]);
                af[mi][2] = __float_as_uint(as[r * ASTRIDE + k8 + l + 4]);
                af[mi][3] = __float_as_uint(as[(r + 8) * ASTRIDE + k8 + l + 4]);
            }
            #pragma unroll
            for (int ni = 0; ni < NT8; ni++) {
                int n = warp_n + ni * 8 + g;
                uint32_t b0 = __float_as_uint(bs[(k8 + l) * BSTRIDE + n]);
                uint32_t b1 = __float_as_uint(bs[(k8 + l + 4) * BSTRIDE + n]);
                MMA_TF32(c[0][ni], af[0], b0, b1);
                MMA_TF32(c[1][ni], af[1], b0, b1);
            }
        }

        if (t + 1 < NSTAGE) store_stage(buf ^ 1);
        __syncthreads();
    }

    // ---- epilogue: bias + leaky (+ residual), float2 stores ----
    #pragma unroll
    for (int mi = 0; mi < 2; mi++) {
        #pragma unroll
        for (int ni = 0; ni < NT8; ni++) {
            const int col = colbase + warp_n + ni * 8 + 2 * l;
            const float b0 = bias[col];
            const float b1 = bias[col + 1];
            const int r0 = rowbase + warp_m + mi * 16 + g;
            if (r0 < M) {
                float2 o;
                o.x = leaky(c[mi][ni][0] + b0);
                o.y = leaky(c[mi][ni][1] + b1);
                if (RES) {
                    float2 rv = *reinterpret_cast<const float2*>(
                        res + (size_t)r0 * NOUT + col);
                    o.x += rv.x; o.y += rv.y;
                }
                *reinterpret_cast<float2*>(C + (size_t)r0 * NOUT + col) = o;
            }
            const int r1 = r0 + 8;
            if (r1 < M) {
                float2 o;
                o.x = leaky(c[mi][ni][2] + b0);
                o.y = leaky(c[mi][ni][3] + b1);
                if (RES) {
                    float2 rv = *reinterpret_cast<const float2*>(
                        res + (size_t)r1 * NOUT + col);
                    o.x += rv.x; o.y += rv.y;
                }
                *reinterpret_cast<float2*>(C + (size_t)r1 * NOUT + col) = o;
            }
        }
    }
}

// ---------------------------------------------------------------------------
// LFA: per point n:
//   out[n, 0:D]  = mean_k leaky(geom[n,k,:4] @ Wg[4,D] + bg)
//   out[n, D:2D] = mean_k feat[idx[n,k], 0:D]
// ---------------------------------------------------------------------------
template <int D, int PTS>
__global__ void lfa_kernel(const float* __restrict__ feat,
                           const float* __restrict__ geom,
                           const int*   __restrict__ idx,
                           const float* __restrict__ wg,
                           const float* __restrict__ bg,
                           float* __restrict__ out, int N)
{
    __shared__ float gs[PTS][16][4];
    __shared__ int   is[PTS][16];

    const int tx = threadIdx.x;
    const int ty = threadIdx.y;
    const int p  = blockIdx.x * PTS + ty;
    const bool valid = (p < N);

    if (valid) {
        if (tx < 64)
            (&gs[ty][0][0])[tx] = geom[(size_t)p * 64 + tx];
        if (tx < 16)
            is[ty][tx] = idx[(size_t)p * 16 + tx];
    }
    __syncthreads();
    if (!valid) return;

    const float w0 = wg[0 * D + tx];
    const float w1 = wg[1 * D + tx];
    const float w2 = wg[2 * D + tx];
    const float w3 = wg[3 * D + tx];
    const float bb = bg[tx];

    float gsum = 0.0f, fsum = 0.0f;
    #pragma unroll
    for (int k = 0; k < 16; k++) {
        float v = fmaf(gs[ty][k][0], w0,
                  fmaf(gs[ty][k][1], w1,
                  fmaf(gs[ty][k][2], w2,
                  fmaf(gs[ty][k][3], w3, bb))));
        gsum += leaky(v);
        fsum += feat[(size_t)is[ty][k] * D + tx];
    }
    out[(size_t)p * (2 * D) + tx]     = gsum * 0.0625f;
    out[(size_t)p * (2 * D) + D + tx] = fsum * 0.0625f;
}

// ---------------------------------------------------------------------------
extern "C" void kernel_launch(void* const* d_in, const int* in_sizes, int n_in,
                              void* d_out, int out_size)
{
    const float* X      = (const float*)d_in[0];
    const float* geom   = (const float*)d_in[1];
    const int*   idx    = (const int*)  d_in[2];
    const float* w_res  = (const float*)d_in[3];
    const float* b_res  = (const float*)d_in[4];
    const float* w_init = (const float*)d_in[5];
    const float* b_init = (const float*)d_in[6];
    const float* w_g1   = (const float*)d_in[7];
    const float* b_g1   = (const float*)d_in[8];
    const float* w_g2   = (const float*)d_in[9];
    const float* b_g2   = (const float*)d_in[10];
    const float* w_fin  = (const float*)d_in[11];
    const float* b_fin  = (const float*)d_in[12];
    float* out = (float*)d_out;

    const int N = in_sizes[0] / DIM;

    float *resbuf, *a0buf, *a1buf, *a2buf;
    cudaGetSymbolAddress((void**)&resbuf, g_res);
    cudaGetSymbolAddress((void**)&a0buf,  g_a0);
    cudaGetSymbolAddress((void**)&a1buf,  g_a1);
    cudaGetSymbolAddress((void**)&a2buf,  g_a2);

    const int gridM = (N + 127) / 128;

    // 1) residual = leaky(X @ w_res + b_res)   [N,256]
    mma_gemm<256, 128, false><<<dim3(gridM, 2), 256>>>(X, w_res, b_res,
                                                       nullptr, resbuf, N);
    // 2) a0 = leaky(X @ w_init + b_init)       [N,64]
    mma_gemm<64, 64, false><<<dim3(gridM, 1), 256>>>(X, w_init, b_init,
                                                     nullptr, a0buf, N);
    // 3) a1 = LFA(a0)                          [N,128]
    lfa_kernel<64, 8><<<(N + 7) / 8, dim3(64, 8)>>>(a0buf, geom, idx,
                                                    w_g1, b_g1, a1buf, N);
    // 4) a2 = LFA(a1)                          [N,256]
    lfa_kernel<128, 4><<<(N + 3) / 4, dim3(128, 4)>>>(a1buf, geom, idx,
                                                      w_g2, b_g2, a2buf, N);
    // 5) out = leaky(a2 @ w_fin + b_fin) + residual  [N,256]
    mma_gemm<256, 128, true><<<dim3(gridM, 2), 256>>>(a2buf, w_fin, b_fin,
                                                      resbuf, out, N);
}

// round 4
// speedup vs baseline: 2.6887x; 1.3622x over previous
#include <cuda_runtime.h>
#include <cuda_fp16.h>
#include <cstdint>

#define NPTS 50000
#define DIM 256

// ---------------- scratch (no-alloc rule: __device__ globals) --------------
__device__ float g_res[NPTS * DIM];
__device__ float g_a0 [NPTS * (DIM / 4)];
__device__ float g_a1 [NPTS * (DIM / 2)];
__device__ float g_a2 [NPTS * DIM];
__device__ __half g_wrT[DIM * DIM];        // w_res^T  half [256,256]
__device__ __half g_wiT[(DIM / 4) * DIM];  // w_init^T half [64,256]
__device__ __half g_wfT[DIM * DIM];        // w_fin^T  half [256,256]

__device__ __forceinline__ float leaky(float x) {
    return x >= 0.0f ? x : 0.2f * x;
}

#define MMA_F16(c, a, b0, b1)                                             \
    asm volatile(                                                         \
        "mma.sync.aligned.m16n8k16.row.col.f32.f16.f16.f32 "              \
        "{%0,%1,%2,%3}, {%4,%5,%6,%7}, {%8,%9}, {%0,%1,%2,%3};"           \
        : "+f"((c)[0]), "+f"((c)[1]), "+f"((c)[2]), "+f"((c)[3])          \
        : "r"((a)[0]), "r"((a)[1]), "r"((a)[2]), "r"((a)[3]),             \
          "r"(b0), "r"(b1))

// ---------------------------------------------------------------------------
// Weight prep: fp32 [K,N] -> half [N,K] (convert + transpose)
// ---------------------------------------------------------------------------
__global__ void prep_w(const float* __restrict__ in, __half* __restrict__ out,
                       int K, int N)
{
    __shared__ float t[32][33];
    int k0 = blockIdx.y * 32, n0 = blockIdx.x * 32;
    for (int i = threadIdx.y; i < 32; i += 8)
        t[i][threadIdx.x] = in[(size_t)(k0 + i) * N + n0 + threadIdx.x];
    __syncthreads();
    for (int i = threadIdx.y; i < 32; i += 8)
        out[(size_t)(n0 + i) * K + k0 + threadIdx.x] =
            __float2half(t[threadIdx.x][i]);
}

// ---------------------------------------------------------------------------
// fp16 mma GEMM:  C[M,NOUT] = leaky(A[M,256] @ BtH[NOUT,256]^T + bias) (+res)
// A fp32 row-major (converted to half at STS); BtH half [NOUT,256] k-major.
// CTA tile 128 x CTAN, 8 warps (4m x 2n), warp tile 32 x CTAN/2,
// BK=32 (two k16 mma steps), double-buffered smem, stride-40-half layout.
// ---------------------------------------------------------------------------
template <int NOUT, int CTAN, bool RES>
__global__ __launch_bounds__(256, 2)
void hgemm(const float* __restrict__ A, const __half* __restrict__ Bt,
           const float* __restrict__ bias, const float* __restrict__ res,
           float* __restrict__ C, int M)
{
    constexpr int KDIM   = 256;
    constexpr int BK     = 32;
    constexpr int NSTAGE = KDIM / BK;        // 8
    constexpr int STR    = 40;               // halves per row (pad 8)
    constexpr int NT8    = CTAN / 16;        // n8 tiles per warp
    constexpr int NBLD   = CTAN / 64;        // B uint4 loads per thread

    __shared__ __half As[2][128 * STR];
    __shared__ __half Bs[2][CTAN * STR];

    const int tid  = threadIdx.x;
    const int wid  = tid >> 5;
    const int lane = tid & 31;
    const int g = lane >> 2;
    const int l = lane & 3;
    const int warp_m = (wid & 3) * 32;
    const int warp_n = (wid >> 2) * (CTAN / 2);
    const int rowbase = blockIdx.x * 128;
    const int colbase = blockIdx.y * CTAN;

    float c[2][NT8][4];
    #pragma unroll
    for (int mi = 0; mi < 2; mi++)
        #pragma unroll
        for (int ni = 0; ni < NT8; ni++)
            #pragma unroll
            for (int j = 0; j < 4; j++)
                c[mi][ni][j] = 0.0f;

    float4 aR[4];
    uint4  bR[NBLD];

    // A tile: 128 x 32 fp32 = 1024 float4 (4/thread)
    // B tile: CTAN x 32 half = CTAN*4 uint4 (NBLD/thread)
    auto load_stage = [&](int t) {
        const int kk = t * BK;
        #pragma unroll
        for (int i = 0; i < 4; i++) {
            int e = tid + i * 256;           // 0..1023
            int r = e >> 3, kq = e & 7;
            int grow = rowbase + r;
            aR[i] = (grow < M)
                ? *reinterpret_cast<const float4*>(
                      A + (size_t)grow * KDIM + kk + kq * 4)
                : make_float4(0.f, 0.f, 0.f, 0.f);
        }
        #pragma unroll
        for (int i = 0; i < NBLD; i++) {
            int e = tid + i * 256;           // 0..CTAN*4-1
            int n = e >> 2, kq = e & 3;
            bR[i] = *reinterpret_cast<const uint4*>(
                Bt + (size_t)(colbase + n) * KDIM + kk + kq * 8);
        }
    };

    auto store_stage = [&](int buf) {
        #pragma unroll
        for (int i = 0; i < 4; i++) {
            int e = tid + i * 256;
            int r = e >> 3, kq = e & 7;
            __half2 h0 = __float22half2_rn(make_float2(aR[i].x, aR[i].y));
            __half2 h1 = __float22half2_rn(make_float2(aR[i].z, aR[i].w));
            uint2 v;
            v.x = *reinterpret_cast<uint32_t*>(&h0);
            v.y = *reinterpret_cast<uint32_t*>(&h1);
            *reinterpret_cast<uint2*>(&As[buf][r * STR + kq * 4]) = v;
        }
        #pragma unroll
        for (int i = 0; i < NBLD; i++) {
            int e = tid + i * 256;
            int n = e >> 2, kq = e & 3;
            *reinterpret_cast<uint4*>(&Bs[buf][n * STR + kq * 8]) = bR[i];
        }
    };

    load_stage(0);
    store_stage(0);
    __syncthreads();

    for (int t = 0; t < NSTAGE; t++) {
        const int buf = t & 1;
        if (t + 1 < NSTAGE) load_stage(t + 1);

        const __half* as = As[buf];
        const __half* bs = Bs[buf];
        #pragma unroll
        for (int ks = 0; ks < BK; ks += 16) {
            uint32_t af[2][4];
            #pragma unroll
            for (int mi = 0; mi < 2; mi++) {
                int r = warp_m + mi * 16 + g;
                af[mi][0] = *reinterpret_cast<const uint32_t*>(
                    &as[r * STR + ks + 2 * l]);
                af[mi][1] = *reinterpret_cast<const uint32_t*>(
                    &as[(r + 8) * STR + ks + 2 * l]);
                af[mi][2] = *reinterpret_cast<const uint32_t*>(
                    &as[r * STR + ks + 2 * l + 8]);
                af[mi][3] = *reinterpret_cast<const uint32_t*>(
                    &as[(r + 8) * STR + ks + 2 * l + 8]);
            }
            #pragma unroll
            for (int ni = 0; ni < NT8; ni++) {
                int n = warp_n + ni * 8 + g;
                uint32_t b0 = *reinterpret_cast<const uint32_t*>(
                    &bs[n * STR + ks + 2 * l]);
                uint32_t b1 = *reinterpret_cast<const uint32_t*>(
                    &bs[n * STR + ks + 2 * l + 8]);
                MMA_F16(c[0][ni], af[0], b0, b1);
                MMA_F16(c[1][ni], af[1], b0, b1);
            }
        }

        if (t + 1 < NSTAGE) store_stage(buf ^ 1);
        __syncthreads();
    }

    // ---- epilogue: bias + leaky (+ residual), float2 stores ----
    #pragma unroll
    for (int mi = 0; mi < 2; mi++) {
        #pragma unroll
        for (int ni = 0; ni < NT8; ni++) {
            const int col = colbase + warp_n + ni * 8 + 2 * l;
            const float b0 = bias[col];
            const float b1 = bias[col + 1];
            const int r0 = rowbase + warp_m + mi * 16 + g;
            if (r0 < M) {
                float2 o;
                o.x = leaky(c[mi][ni][0] + b0);
                o.y = leaky(c[mi][ni][1] + b1);
                if (RES) {
                    float2 rv = *reinterpret_cast<const float2*>(
                        res + (size_t)r0 * NOUT + col);
                    o.x += rv.x; o.y += rv.y;
                }
                *reinterpret_cast<float2*>(C + (size_t)r0 * NOUT + col) = o;
            }
            const int r1 = r0 + 8;
            if (r1 < M) {
                float2 o;
                o.x = leaky(c[mi][ni][2] + b0);
                o.y = leaky(c[mi][ni][3] + b1);
                if (RES) {
                    float2 rv = *reinterpret_cast<const float2*>(
                        res + (size_t)r1 * NOUT + col);
                    o.x += rv.x; o.y += rv.y;
                }
                *reinterpret_cast<float2*>(C + (size_t)r1 * NOUT + col) = o;
            }
        }
    }
}

// ---------------------------------------------------------------------------
// LFA (warp-per-point, vector gathers):
//   out[p, 0:D]  = mean_k leaky(geom[p,k,:4] @ Wg[4,D] + bg)
//   out[p, D:2D] = mean_k feat[idx[p,k], 0:D]
// V = D/32 floats per lane (4 for D=128, 2 for D=64). 8 points per 256-thr CTA.
// ---------------------------------------------------------------------------
template <int D>
__global__ __launch_bounds__(256)
void lfa_warp(const float* __restrict__ feat,
              const float* __restrict__ geom,
              const int*   __restrict__ idx,
              const float* __restrict__ wg,
              const float* __restrict__ bg,
              float* __restrict__ out, int N)
{
    constexpr int V = D / 32;
    __shared__ float gs[8][16][4];
    __shared__ int   is[8][16];

    const int tid  = threadIdx.x;
    const int wid  = tid >> 5;
    const int lane = tid & 31;
    const int pbase = blockIdx.x * 8;

    for (int i = tid; i < 8 * 64; i += 256) {
        int pp = pbase + (i >> 6);
        (&gs[0][0][0])[i] = (pp < N) ? geom[(size_t)pp * 64 + (i & 63)] : 0.f;
    }
    for (int i = tid; i < 8 * 16; i += 256) {
        int pp = pbase + (i >> 4);
        is[i >> 4][i & 15] = (pp < N) ? idx[(size_t)pp * 16 + (i & 15)] : 0;
    }
    __syncthreads();

    const int p = pbase + wid;
    if (p >= N) return;

    const int ch0 = lane * V;
    float w[4][V], bb[V];
    #pragma unroll
    for (int cc = 0; cc < V; cc++) {
        bb[cc] = bg[ch0 + cc];
        #pragma unroll
        for (int r = 0; r < 4; r++) w[r][cc] = wg[r * D + ch0 + cc];
    }

    float gsum[V], fsum[V];
    #pragma unroll
    for (int cc = 0; cc < V; cc++) { gsum[cc] = 0.f; fsum[cc] = 0.f; }

    #pragma unroll
    for (int k = 0; k < 16; k++) {
        const float g0 = gs[wid][k][0], g1 = gs[wid][k][1];
        const float g2 = gs[wid][k][2], g3 = gs[wid][k][3];
        const float* fr = feat + (size_t)is[wid][k] * D + ch0;
        float fv[V];
        if constexpr (V == 4) {
            float4 t = *reinterpret_cast<const float4*>(fr);
            fv[0] = t.x; fv[1] = t.y; fv[2] = t.z; fv[3] = t.w;
        } else {
            float2 t = *reinterpret_cast<const float2*>(fr);
            fv[0] = t.x; fv[1] = t.y;
        }
        #pragma unroll
        for (int cc = 0; cc < V; cc++) {
            float v = fmaf(g0, w[0][cc],
                      fmaf(g1, w[1][cc],
                      fmaf(g2, w[2][cc],
                      fmaf(g3, w[3][cc], bb[cc]))));
            gsum[cc] += leaky(v);
            fsum[cc] += fv[cc];
        }
    }

    float* og = out + (size_t)p * (2 * D) + ch0;
    float* of = og + D;
    if constexpr (V == 4) {
        *reinterpret_cast<float4*>(og) = make_float4(
            gsum[0] * 0.0625f, gsum[1] * 0.0625f,
            gsum[2] * 0.0625f, gsum[3] * 0.0625f);
        *reinterpret_cast<float4*>(of) = make_float4(
            fsum[0] * 0.0625f, fsum[1] * 0.0625f,
            fsum[2] * 0.0625f, fsum[3] * 0.0625f);
    } else {
        *reinterpret_cast<float2*>(og) =
            make_float2(gsum[0] * 0.0625f, gsum[1] * 0.0625f);
        *reinterpret_cast<float2*>(of) =
            make_float2(fsum[0] * 0.0625f, fsum[1] * 0.0625f);
    }
}

// ---------------------------------------------------------------------------
extern "C" void kernel_launch(void* const* d_in, const int* in_sizes, int n_in,
                              void* d_out, int out_size)
{
    const float* X      = (const float*)d_in[0];
    const float* geom   = (const float*)d_in[1];
    const int*   idx    = (const int*)  d_in[2];
    const float* w_res  = (const float*)d_in[3];
    const float* b_res  = (const float*)d_in[4];
    const float* w_init = (const float*)d_in[5];
    const float* b_init = (const float*)d_in[6];
    const float* w_g1   = (const float*)d_in[7];
    const float* b_g1   = (const float*)d_in[8];
    const float* w_g2   = (const float*)d_in[9];
    const float* b_g2   = (const float*)d_in[10];
    const float* w_fin  = (const float*)d_in[11];
    const float* b_fin  = (const float*)d_in[12];
    float* out = (float*)d_out;

    const int N = in_sizes[0] / DIM;

    float *resbuf, *a0buf, *a1buf, *a2buf;
    __half *wrT, *wiT, *wfT;
    cudaGetSymbolAddress((void**)&resbuf, g_res);
    cudaGetSymbolAddress((void**)&a0buf,  g_a0);
    cudaGetSymbolAddress((void**)&a1buf,  g_a1);
    cudaGetSymbolAddress((void**)&a2buf,  g_a2);
    cudaGetSymbolAddress((void**)&wrT,    g_wrT);
    cudaGetSymbolAddress((void**)&wiT,    g_wiT);
    cudaGetSymbolAddress((void**)&wfT,    g_wfT);

    // weight prep: fp32 [K,N] -> half [N,K]
    prep_w<<<dim3(8, 8), dim3(32, 8)>>>(w_res,  wrT, DIM, DIM);
    prep_w<<<dim3(2, 8), dim3(32, 8)>>>(w_init, wiT, DIM, DIM / 4);
    prep_w<<<dim3(8, 8), dim3(32, 8)>>>(w_fin,  wfT, DIM, DIM);

    const int gridM = (N + 127) / 128;

    // 1) residual = leaky(X @ w_res + b_res)   [N,256]
    hgemm<256, 128, false><<<dim3(gridM, 2), 256>>>(X, wrT, b_res,
                                                    nullptr, resbuf, N);
    // 2) a0 = leaky(X @ w_init + b_init)       [N,64]
    hgemm<64, 64, false><<<dim3(gridM, 1), 256>>>(X, wiT, b_init,
                                                  nullptr, a0buf, N);
    // 3) a1 = LFA(a0)                          [N,128]
    lfa_warp<64><<<(N + 7) / 8, 256>>>(a0buf, geom, idx, w_g1, b_g1, a1buf, N);
    // 4) a2 = LFA(a1)                          [N,256]
    lfa_warp<128><<<(N + 7) / 8, 256>>>(a1buf, geom, idx, w_g2, b_g2, a2buf, N);
    // 5) out = leaky(a2 @ w_fin + b_fin) + residual  [N,256]
    hgemm<256, 128, true><<<dim3(gridM, 2), 256>>>(a2buf, wfT, b_fin,
                                                   resbuf, out, N);
}

// round 5
// speedup vs baseline: 2.9108x; 1.0826x over previous
#include <cuda_runtime.h>
#include <cuda_fp16.h>
#include <cstdint>

#define NPTS 50000
#define DIM 256

// ---------------- scratch (no-alloc rule: __device__ globals) --------------
__device__ float  g_res[NPTS * DIM];
__device__ float  g_a0 [NPTS * (DIM / 4)];
__device__ float  g_a1 [NPTS * (DIM / 2)];
__device__ __half g_xh [NPTS * DIM];       // X converted to half
__device__ __half g_a2h[NPTS * DIM];       // LFA2 output, half
__device__ __half g_wrT[DIM * DIM];        // w_res^T  half [256,256]
__device__ __half g_wiT[(DIM / 4) * DIM];  // w_init^T half [64,256]
__device__ __half g_wfT[DIM * DIM];        // w_fin^T  half [256,256]

__device__ __forceinline__ float leaky(float x) {
    return x >= 0.0f ? x : 0.2f * x;
}

#define MMA_F16(c, a, b0, b1)                                             \
    asm volatile(                                                         \
        "mma.sync.aligned.m16n8k16.row.col.f32.f16.f16.f32 "              \
        "{%0,%1,%2,%3}, {%4,%5,%6,%7}, {%8,%9}, {%0,%1,%2,%3};"           \
        : "+f"((c)[0]), "+f"((c)[1]), "+f"((c)[2]), "+f"((c)[3])          \
        : "r"((a)[0]), "r"((a)[1]), "r"((a)[2]), "r"((a)[3]),             \
          "r"(b0), "r"(b1))

#define LDSM_X4(r0, r1, r2, r3, addr)                                     \
    asm volatile(                                                         \
        "ldmatrix.sync.aligned.m8n8.x4.shared.b16 {%0,%1,%2,%3}, [%4];"   \
        : "=r"(r0), "=r"(r1), "=r"(r2), "=r"(r3) : "r"(addr))

__device__ __forceinline__ void cp_async16(uint32_t dst, const void* src,
                                           uint32_t src_bytes) {
    asm volatile("cp.async.ca.shared.global [%0], [%1], 16, %2;"
                 :: "r"(dst), "l"(src), "r"(src_bytes));
}
#define CP_COMMIT() asm volatile("cp.async.commit_group;")
#define CP_WAIT(n)  asm volatile("cp.async.wait_group %0;" :: "n"(n))

// ---------------------------------------------------------------------------
// Weight prep: fp32 [K,N] -> half [N,K] (convert + transpose)
// ---------------------------------------------------------------------------
__global__ void prep_w(const float* __restrict__ in, __half* __restrict__ out,
                       int K, int N)
{
    __shared__ float t[32][33];
    int k0 = blockIdx.y * 32, n0 = blockIdx.x * 32;
    for (int i = threadIdx.y; i < 32; i += 8)
        t[i][threadIdx.x] = in[(size_t)(k0 + i) * N + n0 + threadIdx.x];
    __syncthreads();
    for (int i = threadIdx.y; i < 32; i += 8)
        out[(size_t)(n0 + i) * K + k0 + threadIdx.x] =
            __float2half(t[threadIdx.x][i]);
}

// fp32 -> half streaming convert (4 floats / thread)
__global__ void cvt_f2h(const float4* __restrict__ in,
                        uint2* __restrict__ out, int n4)
{
    int i = blockIdx.x * blockDim.x + threadIdx.x;
    if (i < n4) {
        float4 v = in[i];
        __half2 a = __float22half2_rn(make_float2(v.x, v.y));
        __half2 b = __float22half2_rn(make_float2(v.z, v.w));
        uint2 o;
        o.x = *reinterpret_cast<uint32_t*>(&a);
        o.y = *reinterpret_cast<uint32_t*>(&b);
        out[i] = o;
    }
}

// ---------------------------------------------------------------------------
// half mma GEMM with cp.async + ldmatrix:
//   C[M,NOUT] = leaky(Ah[M,256] @ BtH[NOUT,256]^T + bias) (+res)
// Ah half row-major; BtH half [NOUT,256] k-major.
// CTA tile 128 x CTAN, 8 warps (4m x 2n), BK=64 (128B rows, XOR-8 swizzle),
// 2-stage cp.async pipeline, ldmatrix.x4 fragment loads.
// ---------------------------------------------------------------------------
template <int NOUT, int CTAN, bool RES>
__global__ __launch_bounds__(256, 2)
void hgemm2(const __half* __restrict__ A, const __half* __restrict__ Bt,
            const float* __restrict__ bias, const float* __restrict__ res,
            float* __restrict__ C, int M)
{
    constexpr int KD    = 256;
    constexpr int BK    = 64;                // halves per stage-row (128B)
    constexpr int NST   = KD / BK;           // 4
    constexpr int ABY   = 128 * 128;         // A stage bytes
    constexpr int BBY   = CTAN * 128;        // B stage bytes
    constexpr int STAGE = ABY + BBY;
    constexpr int NT16  = CTAN / 32;         // n16 dual-tiles per warp
    constexpr int NT8   = 2 * NT16;
    constexpr int BLD   = CTAN / 32;         // B cp.async per thread

    extern __shared__ char smem[];
    const uint32_t sbase =
        (uint32_t)__cvta_generic_to_shared(smem);

    const int tid  = threadIdx.x;
    const int wid  = tid >> 5;
    const int lane = tid & 31;
    const int g = lane >> 2;
    const int l = lane & 3;
    const int quad = lane >> 3;
    const int lrow = lane & 7;
    const int warp_m = (wid & 3) * 32;
    const int warp_n = (wid >> 2) * (CTAN / 2);
    const int rowbase = blockIdx.x * 128;
    const int colbase = blockIdx.y * CTAN;

    // producer chunk coords (16B chunks; 8 per 128B row)
    const int pa_r = tid >> 3, pa_c = tid & 7;   // +128 rows per i-step (A)

    // ldmatrix lane-row / swizzle precompute
    const int arow = warp_m + (quad & 1) * 8 + lrow;        // + mi*16
    const int ac_hi = quad >> 1;                            // k-chunk bit
    const int brow0 = warp_n + ((quad >> 1) & 1) * 8 + lrow; // + nt*16
    const int bc_lo = quad & 1;

    float c[2][NT8][4];
    #pragma unroll
    for (int mi = 0; mi < 2; mi++)
        #pragma unroll
        for (int ni = 0; ni < NT8; ni++)
            #pragma unroll
            for (int j = 0; j < 4; j++)
                c[mi][ni][j] = 0.0f;

    auto issue = [&](int t) {
        const int kk = t * BK;
        const uint32_t st = sbase + (t & 1) * STAGE;
        #pragma unroll
        for (int i = 0; i < 4; i++) {               // A: 1024 chunks
            int r = pa_r + i * 32;
            int grow = rowbase + r;
            bool v = grow < M;
            const __half* src =
                A + (size_t)(v ? grow : 0) * KD + kk + pa_c * 8;
            uint32_t dst = st + r * 128 + ((pa_c ^ (r & 7)) << 4);
            cp_async16(dst, src, v ? 16u : 0u);
        }
        #pragma unroll
        for (int i = 0; i < BLD; i++) {             // B: CTAN*8 chunks
            int r = pa_r + i * 32;
            const __half* src =
                Bt + (size_t)(colbase + r) * KD + kk + pa_c * 8;
            uint32_t dst = st + ABY + r * 128 + ((pa_c ^ (r & 7)) << 4);
            cp_async16(dst, src, 16u);
        }
        CP_COMMIT();
    };

    issue(0);
    issue(1);
    CP_WAIT(1);
    __syncthreads();

    for (int t = 0; t < NST; t++) {
        const uint32_t st = sbase + (t & 1) * STAGE;
        #pragma unroll
        for (int ks8 = 0; ks8 < BK / 8; ks8 += 2) {  // k16 steps
            uint32_t af[2][4];
            #pragma unroll
            for (int mi = 0; mi < 2; mi++) {
                int r = arow + mi * 16;
                int cch = ks8 + ac_hi;
                uint32_t addr = st + r * 128 + ((cch ^ (r & 7)) << 4);
                LDSM_X4(af[mi][0], af[mi][1], af[mi][2], af[mi][3], addr);
            }
            uint32_t bf[NT16][4];
            #pragma unroll
            for (int nt = 0; nt < NT16; nt++) {
                int r = brow0 + nt * 16;
                int cch = ks8 + bc_lo;
                uint32_t addr = st + ABY + r * 128 + ((cch ^ (r & 7)) << 4);
                LDSM_X4(bf[nt][0], bf[nt][1], bf[nt][2], bf[nt][3], addr);
            }
            #pragma unroll
            for (int nt = 0; nt < NT16; nt++) {
                MMA_F16(c[0][nt * 2 + 0], af[0], bf[nt][0], bf[nt][1]);
                MMA_F16(c[1][nt * 2 + 0], af[1], bf[nt][0], bf[nt][1]);
                MMA_F16(c[0][nt * 2 + 1], af[0], bf[nt][2], bf[nt][3]);
                MMA_F16(c[1][nt * 2 + 1], af[1], bf[nt][2], bf[nt][3]);
            }
        }
        __syncthreads();
        if (t + 1 < NST) {
            if (t + 2 < NST) { issue(t + 2); CP_WAIT(1); }
            else             { CP_WAIT(0); }
            __syncthreads();
        }
    }

    // ---- epilogue: bias + leaky (+ residual), float2 stores ----
    #pragma unroll
    for (int mi = 0; mi < 2; mi++) {
        #pragma unroll
        for (int ni = 0; ni < NT8; ni++) {
            const int col = colbase + warp_n + ni * 8 + 2 * l;
            const float b0 = bias[col];
            const float b1 = bias[col + 1];
            const int r0 = rowbase + warp_m + mi * 16 + g;
            if (r0 < M) {
                float2 o;
                o.x = leaky(c[mi][ni][0] + b0);
                o.y = leaky(c[mi][ni][1] + b1);
                if (RES) {
                    float2 rv = *reinterpret_cast<const float2*>(
                        res + (size_t)r0 * NOUT + col);
                    o.x += rv.x; o.y += rv.y;
                }
                *reinterpret_cast<float2*>(C + (size_t)r0 * NOUT + col) = o;
            }
            const int r1 = r0 + 8;
            if (r1 < M) {
                float2 o;
                o.x = leaky(c[mi][ni][2] + b0);
                o.y = leaky(c[mi][ni][3] + b1);
                if (RES) {
                    float2 rv = *reinterpret_cast<const float2*>(
                        res + (size_t)r1 * NOUT + col);
                    o.x += rv.x; o.y += rv.y;
                }
                *reinterpret_cast<float2*>(C + (size_t)r1 * NOUT + col) = o;
            }
        }
    }
}

// ---------------------------------------------------------------------------
// LFA (warp-per-point, vector gathers). HALF_OUT writes __half output.
// ---------------------------------------------------------------------------
template <int D, bool HALF_OUT>
__global__ __launch_bounds__(256)
void lfa_warp(const float* __restrict__ feat,
              const float* __restrict__ geom,
              const int*   __restrict__ idx,
              const float* __restrict__ wg,
              const float* __restrict__ bg,
              void* __restrict__ outp, int N)
{
    constexpr int V = D / 32;
    __shared__ float gs[8][16][4];
    __shared__ int   is[8][16];

    const int tid  = threadIdx.x;
    const int wid  = tid >> 5;
    const int lane = tid & 31;
    const int pbase = blockIdx.x * 8;

    for (int i = tid; i < 8 * 64; i += 256) {
        int pp = pbase + (i >> 6);
        (&gs[0][0][0])[i] = (pp < N) ? geom[(size_t)pp * 64 + (i & 63)] : 0.f;
    }
    for (int i = tid; i < 8 * 16; i += 256) {
        int pp = pbase + (i >> 4);
        is[i >> 4][i & 15] = (pp < N) ? idx[(size_t)pp * 16 + (i & 15)] : 0;
    }
    __syncthreads();

    const int p = pbase + wid;
    if (p >= N) return;

    const int ch0 = lane * V;
    float w[4][V], bb[V];
    #pragma unroll
    for (int cc = 0; cc < V; cc++) {
        bb[cc] = bg[ch0 + cc];
        #pragma unroll
        for (int r = 0; r < 4; r++) w[r][cc] = wg[r * D + ch0 + cc];
    }

    float gsum[V], fsum[V];
    #pragma unroll
    for (int cc = 0; cc < V; cc++) { gsum[cc] = 0.f; fsum[cc] = 0.f; }

    #pragma unroll
    for (int k = 0; k < 16; k++) {
        const float g0 = gs[wid][k][0], g1 = gs[wid][k][1];
        const float g2 = gs[wid][k][2], g3 = gs[wid][k][3];
        const float* fr = feat + (size_t)is[wid][k] * D + ch0;
        float fv[V];
        if constexpr (V == 4) {
            float4 t = *reinterpret_cast<const float4*>(fr);
            fv[0] = t.x; fv[1] = t.y; fv[2] = t.z; fv[3] = t.w;
        } else {
            float2 t = *reinterpret_cast<const float2*>(fr);
            fv[0] = t.x; fv[1] = t.y;
        }
        #pragma unroll
        for (int cc = 0; cc < V; cc++) {
            float v = fmaf(g0, w[0][cc],
                      fmaf(g1, w[1][cc],
                      fmaf(g2, w[2][cc],
                      fmaf(g3, w[3][cc], bb[cc]))));
            gsum[cc] += leaky(v);
            fsum[cc] += fv[cc];
        }
    }
    #pragma unroll
    for (int cc = 0; cc < V; cc++) { gsum[cc] *= 0.0625f; fsum[cc] *= 0.0625f; }

    if constexpr (HALF_OUT) {
        __half* out = (__half*)outp;
        __half* og = out + (size_t)p * (2 * D) + ch0;
        __half* of = og + D;
        if constexpr (V == 4) {
            __half2 h0 = __float22half2_rn(make_float2(gsum[0], gsum[1]));
            __half2 h1 = __float22half2_rn(make_float2(gsum[2], gsum[3]));
            uint2 u; u.x = *reinterpret_cast<uint32_t*>(&h0);
            u.y = *reinterpret_cast<uint32_t*>(&h1);
            *reinterpret_cast<uint2*>(og) = u;
            __half2 f0 = __float22half2_rn(make_float2(fsum[0], fsum[1]));
            __half2 f1 = __float22half2_rn(make_float2(fsum[2], fsum[3]));
            uint2 v; v.x = *reinterpret_cast<uint32_t*>(&f0);
            v.y = *reinterpret_cast<uint32_t*>(&f1);
            *reinterpret_cast<uint2*>(of) = v;
        } else {
            __half2 h0 = __float22half2_rn(make_float2(gsum[0], gsum[1]));
            *reinterpret_cast<uint32_t*>(og) = *reinterpret_cast<uint32_t*>(&h0);
            __half2 f0 = __float22half2_rn(make_float2(fsum[0], fsum[1]));
            *reinterpret_cast<uint32_t*>(of) = *reinterpret_cast<uint32_t*>(&f0);
        }
    } else {
        float* out = (float*)outp;
        float* og = out + (size_t)p * (2 * D) + ch0;
        float* of = og + D;
        if constexpr (V == 4) {
            *reinterpret_cast<float4*>(og) =
                make_float4(gsum[0], gsum[1], gsum[2], gsum[3]);
            *reinterpret_cast<float4*>(of) =
                make_float4(fsum[0], fsum[1], fsum[2], fsum[3]);
        } else {
            *reinterpret_cast<float2*>(og) = make_float2(gsum[0], gsum[1]);
            *reinterpret_cast<float2*>(of) = make_float2(fsum[0], fsum[1]);
        }
    }
}

// ---------------------------------------------------------------------------
extern "C" void kernel_launch(void* const* d_in, const int* in_sizes, int n_in,
                              void* d_out, int out_size)
{
    const float* X      = (const float*)d_in[0];
    const float* geom   = (const float*)d_in[1];
    const int*   idx    = (const int*)  d_in[2];
    const float* w_res  = (const float*)d_in[3];
    const float* b_res  = (const float*)d_in[4];
    const float* w_init = (const float*)d_in[5];
    const float* b_init = (const float*)d_in[6];
    const float* w_g1   = (const float*)d_in[7];
    const float* b_g1   = (const float*)d_in[8];
    const float* w_g2   = (const float*)d_in[9];
    const float* b_g2   = (const float*)d_in[10];
    const float* w_fin  = (const float*)d_in[11];
    const float* b_fin  = (const float*)d_in[12];
    float* out = (float*)d_out;

    const int N = in_sizes[0] / DIM;

    float *resbuf, *a0buf, *a1buf;
    __half *xh, *a2h, *wrT, *wiT, *wfT;
    cudaGetSymbolAddress((void**)&resbuf, g_res);
    cudaGetSymbolAddress((void**)&a0buf,  g_a0);
    cudaGetSymbolAddress((void**)&a1buf,  g_a1);
    cudaGetSymbolAddress((void**)&xh,     g_xh);
    cudaGetSymbolAddress((void**)&a2h,    g_a2h);
    cudaGetSymbolAddress((void**)&wrT,    g_wrT);
    cudaGetSymbolAddress((void**)&wiT,    g_wiT);
    cudaGetSymbolAddress((void**)&wfT,    g_wfT);

    // one-time smem attribute setup (host-side, not captured as graph nodes)
    constexpr int SMEM_BIG   = 2 * (128 * 128 + 128 * 128);  // 64 KB
    constexpr int SMEM_SMALL = 2 * (128 * 128 + 64 * 128);   // 48 KB
    cudaFuncSetAttribute(hgemm2<256, 128, false>,
                         cudaFuncAttributeMaxDynamicSharedMemorySize, SMEM_BIG);
    cudaFuncSetAttribute(hgemm2<256, 128, true>,
                         cudaFuncAttributeMaxDynamicSharedMemorySize, SMEM_BIG);
    cudaFuncSetAttribute(hgemm2<64, 64, false>,
                         cudaFuncAttributeMaxDynamicSharedMemorySize, SMEM_SMALL);

    // weight prep + activation convert
    prep_w<<<dim3(8, 8), dim3(32, 8)>>>(w_res,  wrT, DIM, DIM);
    prep_w<<<dim3(2, 8), dim3(32, 8)>>>(w_init, wiT, DIM, DIM / 4);
    prep_w<<<dim3(8, 8), dim3(32, 8)>>>(w_fin,  wfT, DIM, DIM);
    const int n4 = N * DIM / 4;
    cvt_f2h<<<(n4 + 255) / 256, 256>>>((const float4*)X, (uint2*)xh, n4);

    const int gridM = (N + 127) / 128;

    // 1) residual = leaky(X @ w_res + b_res)   [N,256]
    hgemm2<256, 128, false><<<dim3(gridM, 2), 256, SMEM_BIG>>>(
        xh, wrT, b_res, nullptr, resbuf, N);
    // 2) a0 = leaky(X @ w_init + b_init)       [N,64]
    hgemm2<64, 64, false><<<dim3(gridM, 1), 256, SMEM_SMALL>>>(
        xh, wiT, b_init, nullptr, a0buf, N);
    // 3) a1 = LFA(a0)                          [N,128] fp32
    lfa_warp<64, false><<<(N + 7) / 8, 256>>>(a0buf, geom, idx,
                                              w_g1, b_g1, a1buf, N);
    // 4) a2 = LFA(a1)                          [N,256] half
    lfa_warp<128, true><<<(N + 7) / 8, 256>>>(a1buf, geom, idx,
                                              w_g2, b_g2, a2h, N);
    // 5) out = leaky(a2 @ w_fin + b_fin) + residual  [N,256]
    hgemm2<256, 128, true><<<dim3(gridM, 2), 256, SMEM_BIG>>>(
        a2h, wfT, b_fin, resbuf, out, N);
}

// round 6
// speedup vs baseline: 3.0674x; 1.0538x over previous
#include <cuda_runtime.h>
#include <cuda_fp16.h>
#include <cstdint>

#define NPTS 50000
#define DIM 256

// ---------------- scratch (no-alloc rule: __device__ globals) --------------
__device__ float  g_res[NPTS * DIM];        // residual, fp32
__device__ __half g_a0h[NPTS * (DIM / 4)];  // init MLP out, half
__device__ __half g_a1h[NPTS * (DIM / 2)];  // LFA1 out, half
__device__ __half g_a2h[NPTS * DIM];        // LFA2 out, half
__device__ __half g_xh [NPTS * DIM];        // X converted to half
__device__ __half g_wcat[(DIM + DIM / 4) * DIM]; // [w_res^T ; w_init^T] [320,256]
__device__ __half g_wfT[DIM * DIM];         // w_fin^T half [256,256]

__device__ __forceinline__ float leaky(float x) {
    return x >= 0.0f ? x : 0.2f * x;
}

#define MMA_F16(c, a, b0, b1)                                             \
    asm volatile(                                                         \
        "mma.sync.aligned.m16n8k16.row.col.f32.f16.f16.f32 "              \
        "{%0,%1,%2,%3}, {%4,%5,%6,%7}, {%8,%9}, {%0,%1,%2,%3};"           \
        : "+f"((c)[0]), "+f"((c)[1]), "+f"((c)[2]), "+f"((c)[3])          \
        : "r"((a)[0]), "r"((a)[1]), "r"((a)[2]), "r"((a)[3]),             \
          "r"(b0), "r"(b1))

#define LDSM_X4(r0, r1, r2, r3, addr)                                     \
    asm volatile(                                                         \
        "ldmatrix.sync.aligned.m8n8.x4.shared.b16 {%0,%1,%2,%3}, [%4];"   \
        : "=r"(r0), "=r"(r1), "=r"(r2), "=r"(r3) : "r"(addr))

__device__ __forceinline__ void cp_async16(uint32_t dst, const void* src,
                                           uint32_t src_bytes) {
    asm volatile("cp.async.ca.shared.global [%0], [%1], 16, %2;"
                 :: "r"(dst), "l"(src), "r"(src_bytes));
}
#define CP_COMMIT() asm volatile("cp.async.commit_group;")
#define CP_WAIT(n)  asm volatile("cp.async.wait_group %0;" :: "n"(n))

// ---------------------------------------------------------------------------
// Weight prep: fp32 [K,N] -> half [N,K] (convert + transpose)
// ---------------------------------------------------------------------------
__global__ void prep_w(const float* __restrict__ in, __half* __restrict__ out,
                       int K, int N)
{
    __shared__ float t[32][33];
    int k0 = blockIdx.y * 32, n0 = blockIdx.x * 32;
    for (int i = threadIdx.y; i < 32; i += 8)
        t[i][threadIdx.x] = in[(size_t)(k0 + i) * N + n0 + threadIdx.x];
    __syncthreads();
    for (int i = threadIdx.y; i < 32; i += 8)
        out[(size_t)(n0 + i) * K + k0 + threadIdx.x] =
            __float2half(t[threadIdx.x][i]);
}

// fp32 -> half streaming convert (4 floats / thread)
__global__ void cvt_f2h(const float4* __restrict__ in,
                        uint2* __restrict__ out, int n4)
{
    int i = blockIdx.x * blockDim.x + threadIdx.x;
    if (i < n4) {
        float4 v = in[i];
        __half2 a = __float22half2_rn(make_float2(v.x, v.y));
        __half2 b = __float22half2_rn(make_float2(v.z, v.w));
        uint2 o;
        o.x = *reinterpret_cast<uint32_t*>(&a);
        o.y = *reinterpret_cast<uint32_t*>(&b);
        out[i] = o;
    }
}

// ---------------------------------------------------------------------------
// half mma GEMM, cp.async + ldmatrix mainloop over K=256.
// MODE 0 (CAT):  CTAN=64, global cols 0..319.
//   cols <256: outF[row*256+col] = leaky(acc + bias0[col])           (fp32)
//   cols>=256: outH[row*64+col-256] = leaky(acc + bias1[col-256])    (half)
// MODE 1 (FINAL): CTAN=128, cols 0..255.
//   outF[row*256+col] = leaky(acc + bias0[col]) + res[row*256+col]   (fp32)
// ---------------------------------------------------------------------------
template <int CTAN, int MODE>
__global__ __launch_bounds__(256, 2)
void hgemm2(const __half* __restrict__ A, const __half* __restrict__ Bt,
            const float* __restrict__ bias0, const float* __restrict__ bias1,
            const float* __restrict__ res, float* __restrict__ outF,
            __half* __restrict__ outH, int M)
{
    constexpr int KD    = 256;
    constexpr int BK    = 64;                // halves per stage-row (128B)
    constexpr int NST   = KD / BK;           // 4
    constexpr int ABY   = 128 * 128;         // A stage bytes
    constexpr int BBY   = CTAN * 128;        // B stage bytes
    constexpr int STAGE = ABY + BBY;
    constexpr int NT16  = CTAN / 32;
    constexpr int NT8   = 2 * NT16;
    constexpr int BLD   = CTAN / 32;

    extern __shared__ char smem[];
    const uint32_t sbase = (uint32_t)__cvta_generic_to_shared(smem);

    const int tid  = threadIdx.x;
    const int wid  = tid >> 5;
    const int lane = tid & 31;
    const int g = lane >> 2;
    const int l = lane & 3;
    const int quad = lane >> 3;
    const int lrow = lane & 7;
    const int warp_m = (wid & 3) * 32;
    const int warp_n = (wid >> 2) * (CTAN / 2);
    const int rowbase = blockIdx.x * 128;
    const int colbase = blockIdx.y * CTAN;

    const int pa_r = tid >> 3, pa_c = tid & 7;

    const int arow  = warp_m + (quad & 1) * 8 + lrow;
    const int ac_hi = quad >> 1;
    const int brow0 = warp_n + ((quad >> 1) & 1) * 8 + lrow;
    const int bc_lo = quad & 1;

    float c[2][NT8][4];
    #pragma unroll
    for (int mi = 0; mi < 2; mi++)
        #pragma unroll
        for (int ni = 0; ni < NT8; ni++)
            #pragma unroll
            for (int j = 0; j < 4; j++)
                c[mi][ni][j] = 0.0f;

    auto issue = [&](int t) {
        const int kk = t * BK;
        const uint32_t st = sbase + (t & 1) * STAGE;
        #pragma unroll
        for (int i = 0; i < 4; i++) {               // A
            int r = pa_r + i * 32;
            int grow = rowbase + r;
            bool v = grow < M;
            const __half* src =
                A + (size_t)(v ? grow : 0) * KD + kk + pa_c * 8;
            uint32_t dst = st + r * 128 + ((pa_c ^ (r & 7)) << 4);
            cp_async16(dst, src, v ? 16u : 0u);
        }
        #pragma unroll
        for (int i = 0; i < BLD; i++) {             // B
            int r = pa_r + i * 32;
            const __half* src =
                Bt + (size_t)(colbase + r) * KD + kk + pa_c * 8;
            uint32_t dst = st + ABY + r * 128 + ((pa_c ^ (r & 7)) << 4);
            cp_async16(dst, src, 16u);
        }
        CP_COMMIT();
    };

    issue(0);
    issue(1);
    CP_WAIT(1);
    __syncthreads();

    for (int t = 0; t < NST; t++) {
        const uint32_t st = sbase + (t & 1) * STAGE;
        #pragma unroll
        for (int ks8 = 0; ks8 < BK / 8; ks8 += 2) {
            uint32_t af[2][4];
            #pragma unroll
            for (int mi = 0; mi < 2; mi++) {
                int r = arow + mi * 16;
                int cch = ks8 + ac_hi;
                uint32_t addr = st + r * 128 + ((cch ^ (r & 7)) << 4);
                LDSM_X4(af[mi][0], af[mi][1], af[mi][2], af[mi][3], addr);
            }
            uint32_t bf[NT16][4];
            #pragma unroll
            for (int nt = 0; nt < NT16; nt++) {
                int r = brow0 + nt * 16;
                int cch = ks8 + bc_lo;
                uint32_t addr = st + ABY + r * 128 + ((cch ^ (r & 7)) << 4);
                LDSM_X4(bf[nt][0], bf[nt][1], bf[nt][2], bf[nt][3], addr);
            }
            #pragma unroll
            for (int nt = 0; nt < NT16; nt++) {
                MMA_F16(c[0][nt * 2 + 0], af[0], bf[nt][0], bf[nt][1]);
                MMA_F16(c[1][nt * 2 + 0], af[1], bf[nt][0], bf[nt][1]);
                MMA_F16(c[0][nt * 2 + 1], af[0], bf[nt][2], bf[nt][3]);
                MMA_F16(c[1][nt * 2 + 1], af[1], bf[nt][2], bf[nt][3]);
            }
        }
        __syncthreads();
        if (t + 1 < NST) {
            if (t + 2 < NST) { issue(t + 2); CP_WAIT(1); }
            else             { CP_WAIT(0); }
            __syncthreads();
        }
    }

    // ---- epilogue ----
    const bool catHalf = (MODE == 0) && (colbase >= 256);
    #pragma unroll
    for (int mi = 0; mi < 2; mi++) {
        #pragma unroll
        for (int ni = 0; ni < NT8; ni++) {
            const int col = colbase + warp_n + ni * 8 + 2 * l;
            float b0, b1;
            if (MODE == 0 && catHalf) {
                b0 = bias1[col - 256];
                b1 = bias1[col - 255];
            } else {
                b0 = bias0[col];
                b1 = bias0[col + 1];
            }
            #pragma unroll
            for (int half_m = 0; half_m < 2; half_m++) {
                const int r = rowbase + warp_m + mi * 16 + g + half_m * 8;
                if (r >= M) continue;
                float ox = leaky(c[mi][ni][half_m * 2 + 0] + b0);
                float oy = leaky(c[mi][ni][half_m * 2 + 1] + b1);
                if (MODE == 1) {
                    float2 rv = *reinterpret_cast<const float2*>(
                        res + (size_t)r * 256 + col);
                    ox += rv.x; oy += rv.y;
                }
                if (MODE == 0 && catHalf) {
                    __half2 h = __float22half2_rn(make_float2(ox, oy));
                    *reinterpret_cast<uint32_t*>(
                        outH + (size_t)r * 64 + col - 256) =
                        *reinterpret_cast<uint32_t*>(&h);
                } else {
                    *reinterpret_cast<float2*>(
                        outF + (size_t)r * 256 + col) = make_float2(ox, oy);
                }
            }
        }
    }
}

// ---------------------------------------------------------------------------
// LFA (warp-per-point): feat is HALF, output HALF.
//   out[p, 0:D]  = mean_k leaky(geom[p,k,:4] @ Wg[4,D] + bg)
//   out[p, D:2D] = mean_k feat[idx[p,k], 0:D]
// ---------------------------------------------------------------------------
template <int D>
__global__ __launch_bounds__(256)
void lfa_half(const __half* __restrict__ feat,
              const float* __restrict__ geom,
              const int*   __restrict__ idx,
              const float* __restrict__ wg,
              const float* __restrict__ bg,
              __half* __restrict__ out, int N)
{
    constexpr int V = D / 32;   // 2 or 4 halves per lane
    __shared__ float gs[8][16][4];
    __shared__ int   is[8][16];

    const int tid  = threadIdx.x;
    const int wid  = tid >> 5;
    const int lane = tid & 31;
    const int pbase = blockIdx.x * 8;

    for (int i = tid; i < 8 * 64; i += 256) {
        int pp = pbase + (i >> 6);
        (&gs[0][0][0])[i] = (pp < N) ? geom[(size_t)pp * 64 + (i & 63)] : 0.f;
    }
    for (int i = tid; i < 8 * 16; i += 256) {
        int pp = pbase + (i >> 4);
        is[i >> 4][i & 15] = (pp < N) ? idx[(size_t)pp * 16 + (i & 15)] : 0;
    }
    __syncthreads();

    const int p = pbase + wid;
    if (p >= N) return;

    const int ch0 = lane * V;
    float w[4][V], bb[V];
    #pragma unroll
    for (int cc = 0; cc < V; cc++) {
        bb[cc] = bg[ch0 + cc];
        #pragma unroll
        for (int r = 0; r < 4; r++) w[r][cc] = wg[r * D + ch0 + cc];
    }

    float gsum[V], fsum[V];
    #pragma unroll
    for (int cc = 0; cc < V; cc++) { gsum[cc] = 0.f; fsum[cc] = 0.f; }

    #pragma unroll
    for (int k = 0; k < 16; k++) {
        const float g0 = gs[wid][k][0], g1 = gs[wid][k][1];
        const float g2 = gs[wid][k][2], g3 = gs[wid][k][3];
        const __half* fr = feat + (size_t)is[wid][k] * D + ch0;
        float fv[V];
        if constexpr (V == 4) {
            uint2 u = *reinterpret_cast<const uint2*>(fr);
            float2 f0 = __half22float2(*reinterpret_cast<__half2*>(&u.x));
            float2 f1 = __half22float2(*reinterpret_cast<__half2*>(&u.y));
            fv[0] = f0.x; fv[1] = f0.y; fv[2] = f1.x; fv[3] = f1.y;
        } else {
            uint32_t u = *reinterpret_cast<const uint32_t*>(fr);
            float2 f0 = __half22float2(*reinterpret_cast<__half2*>(&u));
            fv[0] = f0.x; fv[1] = f0.y;
        }
        #pragma unroll
        for (int cc = 0; cc < V; cc++) {
            float v = fmaf(g0, w[0][cc],
                      fmaf(g1, w[1][cc],
                      fmaf(g2, w[2][cc],
                      fmaf(g3, w[3][cc], bb[cc]))));
            gsum[cc] += leaky(v);
            fsum[cc] += fv[cc];
        }
    }

    __half* og = out + (size_t)p * (2 * D) + ch0;
    __half* of = og + D;
    if constexpr (V == 4) {
        __half2 h0 = __float22half2_rn(
            make_float2(gsum[0] * 0.0625f, gsum[1] * 0.0625f));
        __half2 h1 = __float22half2_rn(
            make_float2(gsum[2] * 0.0625f, gsum[3] * 0.0625f));
        uint2 u;
        u.x = *reinterpret_cast<uint32_t*>(&h0);
        u.y = *reinterpret_cast<uint32_t*>(&h1);
        *reinterpret_cast<uint2*>(og) = u;
        __half2 f0 = __float22half2_rn(
            make_float2(fsum[0] * 0.0625f, fsum[1] * 0.0625f));
        __half2 f1 = __float22half2_rn(
            make_float2(fsum[2] * 0.0625f, fsum[3] * 0.0625f));
        uint2 v;
        v.x = *reinterpret_cast<uint32_t*>(&f0);
        v.y = *reinterpret_cast<uint32_t*>(&f1);
        *reinterpret_cast<uint2*>(of) = v;
    } else {
        __half2 h0 = __float22half2_rn(
            make_float2(gsum[0] * 0.0625f, gsum[1] * 0.0625f));
        *reinterpret_cast<uint32_t*>(og) = *reinterpret_cast<uint32_t*>(&h0);
        __half2 f0 = __float22half2_rn(
            make_float2(fsum[0] * 0.0625f, fsum[1] * 0.0625f));
        *reinterpret_cast<uint32_t*>(of) = *reinterpret_cast<uint32_t*>(&f0);
    }
}

// ---------------------------------------------------------------------------
extern "C" void kernel_launch(void* const* d_in, const int* in_sizes, int n_in,
                              void* d_out, int out_size)
{
    const float* X      = (const float*)d_in[0];
    const float* geom   = (const float*)d_in[1];
    const int*   idx    = (const int*)  d_in[2];
    const float* w_res  = (const float*)d_in[3];
    const float* b_res  = (const float*)d_in[4];
    const float* w_init = (const float*)d_in[5];
    const float* b_init = (const float*)d_in[6];
    const float* w_g1   = (const float*)d_in[7];
    const float* b_g1   = (const float*)d_in[8];
    const float* w_g2   = (const float*)d_in[9];
    const float* b_g2   = (const float*)d_in[10];
    const float* w_fin  = (const float*)d_in[11];
    const float* b_fin  = (const float*)d_in[12];
    float* out = (float*)d_out;

    const int N = in_sizes[0] / DIM;

    float *resbuf;
    __half *a0h, *a1h, *a2h, *xh, *wcat, *wfT;
    cudaGetSymbolAddress((void**)&resbuf, g_res);
    cudaGetSymbolAddress((void**)&a0h,    g_a0h);
    cudaGetSymbolAddress((void**)&a1h,    g_a1h);
    cudaGetSymbolAddress((void**)&a2h,    g_a2h);
    cudaGetSymbolAddress((void**)&xh,     g_xh);
    cudaGetSymbolAddress((void**)&wcat,   g_wcat);
    cudaGetSymbolAddress((void**)&wfT,    g_wfT);

    constexpr int SMEM_CAT   = 2 * (128 * 128 + 64 * 128);   // 48 KB
    constexpr int SMEM_FINAL = 2 * (128 * 128 + 128 * 128);  // 64 KB
    cudaFuncSetAttribute(hgemm2<64, 0>,
                         cudaFuncAttributeMaxDynamicSharedMemorySize, SMEM_CAT);
    cudaFuncSetAttribute(hgemm2<128, 1>,
                         cudaFuncAttributeMaxDynamicSharedMemorySize, SMEM_FINAL);

    // weight prep: wcat = [w_res^T (256 rows) ; w_init^T (64 rows)], wfT
    prep_w<<<dim3(8, 8), dim3(32, 8)>>>(w_res,  wcat, DIM, DIM);
    prep_w<<<dim3(2, 8), dim3(32, 8)>>>(w_init, wcat + DIM * DIM, DIM, DIM / 4);
    prep_w<<<dim3(8, 8), dim3(32, 8)>>>(w_fin,  wfT, DIM, DIM);
    const int n4 = N * DIM / 4;
    cvt_f2h<<<(n4 + 255) / 256, 256>>>((const float4*)X, (uint2*)xh, n4);

    const int gridM = (N + 127) / 128;

    // 1+2) fused: residual (fp32) + a0 (half) = leaky(X @ [w_res|w_init] + b)
    hgemm2<64, 0><<<dim3(gridM, 5), 256, SMEM_CAT>>>(
        xh, wcat, b_res, b_init, nullptr, resbuf, a0h, N);
    // 3) a1 = LFA(a0)  [N,128] half
    lfa_half<64><<<(N + 7) / 8, 256>>>(a0h, geom, idx, w_g1, b_g1, a1h, N);
    // 4) a2 = LFA(a1)  [N,256] half
    lfa_half<128><<<(N + 7) / 8, 256>>>(a1h, geom, idx, w_g2, b_g2, a2h, N);
    // 5) out = leaky(a2 @ w_fin + b_fin) + residual
    hgemm2<128, 1><<<dim3(gridM, 2), 256, SMEM_FINAL>>>(
        a2h, wfT, b_fin, nullptr, resbuf, out, nullptr, N);
}

// round 7
// speedup vs baseline: 3.2089x; 1.0462x over previous
#include <cuda_runtime.h>
#include <cuda_fp16.h>
#include <cstdint>

#define NPTS 50000
#define DIM 256

// ---------------- scratch (no-alloc rule: __device__ globals) --------------
__device__ __half g_resh[NPTS * DIM];       // residual, half
__device__ __half g_a0h[NPTS * (DIM / 4)];  // init MLP out, half
__device__ __half g_a1h[NPTS * (DIM / 2)];  // LFA1 out, half
__device__ __half g_a2h[NPTS * DIM];        // LFA2 out, half
__device__ __half g_wcat[(DIM + DIM / 4) * DIM]; // [w_res^T ; w_init^T] [320,256]
__device__ __half g_wfT[DIM * DIM];         // w_fin^T half [256,256]

__device__ __forceinline__ float leaky(float x) {
    return x >= 0.0f ? x : 0.2f * x;
}

#define MMA_F16(c, a, b0, b1)                                             \
    asm volatile(                                                         \
        "mma.sync.aligned.m16n8k16.row.col.f32.f16.f16.f32 "              \
        "{%0,%1,%2,%3}, {%4,%5,%6,%7}, {%8,%9}, {%0,%1,%2,%3};"           \
        : "+f"((c)[0]), "+f"((c)[1]), "+f"((c)[2]), "+f"((c)[3])          \
        : "r"((a)[0]), "r"((a)[1]), "r"((a)[2]), "r"((a)[3]),             \
          "r"(b0), "r"(b1))

#define LDSM_X4(r0, r1, r2, r3, addr)                                     \
    asm volatile(                                                         \
        "ldmatrix.sync.aligned.m8n8.x4.shared.b16 {%0,%1,%2,%3}, [%4];"   \
        : "=r"(r0), "=r"(r1), "=r"(r2), "=r"(r3) : "r"(addr))

__device__ __forceinline__ void cp_async16(uint32_t dst, const void* src,
                                           uint32_t src_bytes) {
    asm volatile("cp.async.ca.shared.global [%0], [%1], 16, %2;"
                 :: "r"(dst), "l"(src), "r"(src_bytes));
}
#define CP_COMMIT() asm volatile("cp.async.commit_group;")
#define CP_WAIT(n)  asm volatile("cp.async.wait_group %0;" :: "n"(n))

// ---------------------------------------------------------------------------
// Merged weight prep: fp32 [K,N] -> half [N,K] for all 3 weights, one launch.
// blocks [0,64): w_res -> wcat rows 0..255
// blocks [64,80): w_init -> wcat rows 256..319
// blocks [80,144): w_fin -> wfT
// ---------------------------------------------------------------------------
__global__ void prep_all(const float* __restrict__ w_res,
                         const float* __restrict__ w_init,
                         const float* __restrict__ w_fin,
                         __half* __restrict__ wcat,
                         __half* __restrict__ wfT)
{
    __shared__ float t[32][33];
    const float* in;
    __half* out;
    int K = 256, N, bx;
    if (blockIdx.x < 64)      { in = w_res;  out = wcat; N = 256; bx = blockIdx.x; }
    else if (blockIdx.x < 80) { in = w_init; out = wcat + 256 * 256; N = 64;
                                bx = blockIdx.x - 64; }
    else                      { in = w_fin;  out = wfT;  N = 256; bx = blockIdx.x - 80; }
    int nTx = N / 32;
    int n0 = (bx % nTx) * 32;
    int k0 = (bx / nTx) * 32;
    for (int i = threadIdx.y; i < 32; i += 8)
        t[i][threadIdx.x] = in[(size_t)(k0 + i) * N + n0 + threadIdx.x];
    __syncthreads();
    for (int i = threadIdx.y; i < 32; i += 8)
        out[(size_t)(n0 + i) * K + k0 + threadIdx.x] =
            __float2half(t[threadIdx.x][i]);
}

// ---------------------------------------------------------------------------
// CAT GEMM (fused stage 1+2): A = X fp32 [M,256] (inline cvt at STS),
// B = wcat half [320,256] k-major.  CTAN=64, grid.y=5 (cols 0..319).
//   cols <256: resh[row*256+col] = leaky(acc + b_res[col])   (half)
//   cols>=256: a0h[row*64+col-256] = leaky(acc + b_init[..]) (half)
// ---------------------------------------------------------------------------
__global__ __launch_bounds__(256, 2)
void hgemm_cat(const float* __restrict__ A, const __half* __restrict__ Bt,
               const float* __restrict__ bias0, const float* __restrict__ bias1,
               __half* __restrict__ resh, __half* __restrict__ a0h, int M)
{
    constexpr int KD    = 256;
    constexpr int BK    = 64;
    constexpr int NST   = KD / BK;           // 4
    constexpr int CTAN  = 64;
    constexpr int ABY   = 128 * 128;
    constexpr int BBY   = CTAN * 128;
    constexpr int STAGE = ABY + BBY;
    constexpr int NT16  = CTAN / 32;         // 2
    constexpr int NT8   = 2 * NT16;          // 4

    extern __shared__ char smem[];
    const uint32_t sbase = (uint32_t)__cvta_generic_to_shared(smem);

    const int tid  = threadIdx.x;
    const int wid  = tid >> 5;
    const int lane = tid & 31;
    const int g = lane >> 2;
    const int l = lane & 3;
    const int quad = lane >> 3;
    const int lrow = lane & 7;
    const int warp_m = (wid & 3) * 32;
    const int warp_n = (wid >> 2) * (CTAN / 2);
    const int rowbase = blockIdx.x * 128;
    const int colbase = blockIdx.y * CTAN;

    const int pa_r = tid >> 3, pa_c = tid & 7;

    const int arow  = warp_m + (quad & 1) * 8 + lrow;
    const int ac_hi = quad >> 1;
    const int brow0 = warp_n + ((quad >> 1) & 1) * 8 + lrow;
    const int bc_lo = quad & 1;

    float c[2][NT8][4];
    #pragma unroll
    for (int mi = 0; mi < 2; mi++)
        #pragma unroll
        for (int ni = 0; ni < NT8; ni++)
            #pragma unroll
            for (int j = 0; j < 4; j++)
                c[mi][ni][j] = 0.0f;

    float4 aR[4][2];

    auto ldgA = [&](int t) {
        const int kk = t * BK;
        #pragma unroll
        for (int i = 0; i < 4; i++) {
            int r = pa_r + i * 32;
            int grow = rowbase + r;
            if (grow < M) {
                const float4* src = reinterpret_cast<const float4*>(
                    A + (size_t)grow * KD + kk + pa_c * 8);
                aR[i][0] = src[0];
                aR[i][1] = src[1];
            } else {
                aR[i][0] = make_float4(0.f, 0.f, 0.f, 0.f);
                aR[i][1] = make_float4(0.f, 0.f, 0.f, 0.f);
            }
        }
    };

    auto storeA = [&](int t) {
        const uint32_t st = sbase + (t & 1) * STAGE;
        #pragma unroll
        for (int i = 0; i < 4; i++) {
            int r = pa_r + i * 32;
            __half2 h0 = __float22half2_rn(make_float2(aR[i][0].x, aR[i][0].y));
            __half2 h1 = __float22half2_rn(make_float2(aR[i][0].z, aR[i][0].w));
            __half2 h2 = __float22half2_rn(make_float2(aR[i][1].x, aR[i][1].y));
            __half2 h3 = __float22half2_rn(make_float2(aR[i][1].z, aR[i][1].w));
            uint4 v;
            v.x = *reinterpret_cast<uint32_t*>(&h0);
            v.y = *reinterpret_cast<uint32_t*>(&h1);
            v.z = *reinterpret_cast<uint32_t*>(&h2);
            v.w = *reinterpret_cast<uint32_t*>(&h3);
            uint32_t dst = st + r * 128 + ((pa_c ^ (r & 7)) << 4);
            *reinterpret_cast<uint4*>(smem + (dst - sbase)) = v;
        }
    };

    auto issueB = [&](int t) {
        const int kk = t * BK;
        const uint32_t st = sbase + (t & 1) * STAGE;
        #pragma unroll
        for (int i = 0; i < 2; i++) {
            int r = pa_r + i * 32;
            const __half* src =
                Bt + (size_t)(colbase + r) * KD + kk + pa_c * 8;
            uint32_t dst = st + ABY + r * 128 + ((pa_c ^ (r & 7)) << 4);
            cp_async16(dst, src, 16u);
        }
        CP_COMMIT();
    };

    // prologue
    ldgA(0);
    issueB(0);
    issueB(1);
    storeA(0);
    CP_WAIT(1);
    __syncthreads();

    for (int t = 0; t < NST; t++) {
        const uint32_t st = sbase + (t & 1) * STAGE;
        if (t + 1 < NST) ldgA(t + 1);          // LDG in flight during compute

        #pragma unroll
        for (int ks8 = 0; ks8 < BK / 8; ks8 += 2) {
            uint32_t af[2][4];
            #pragma unroll
            for (int mi = 0; mi < 2; mi++) {
                int r = arow + mi * 16;
                int cch = ks8 + ac_hi;
                uint32_t addr = st + r * 128 + ((cch ^ (r & 7)) << 4);
                LDSM_X4(af[mi][0], af[mi][1], af[mi][2], af[mi][3], addr);
            }
            uint32_t bf[NT16][4];
            #pragma unroll
            for (int nt = 0; nt < NT16; nt++) {
                int r = brow0 + nt * 16;
                int cch = ks8 + bc_lo;
                uint32_t addr = st + ABY + r * 128 + ((cch ^ (r & 7)) << 4);
                LDSM_X4(bf[nt][0], bf[nt][1], bf[nt][2], bf[nt][3], addr);
            }
            #pragma unroll
            for (int nt = 0; nt < NT16; nt++) {
                MMA_F16(c[0][nt * 2 + 0], af[0], bf[nt][0], bf[nt][1]);
                MMA_F16(c[1][nt * 2 + 0], af[1], bf[nt][0], bf[nt][1]);
                MMA_F16(c[0][nt * 2 + 1], af[0], bf[nt][2], bf[nt][3]);
                MMA_F16(c[1][nt * 2 + 1], af[1], bf[nt][2], bf[nt][3]);
            }
        }
        __syncthreads();
        if (t + 1 < NST) {
            storeA(t + 1);
            if (t + 2 < NST) { issueB(t + 2); CP_WAIT(1); }
            else             { CP_WAIT(0); }
            __syncthreads();
        }
    }

    // ---- epilogue: bias + leaky, half outputs ----
    const bool isInit = (colbase >= 256);
    #pragma unroll
    for (int mi = 0; mi < 2; mi++) {
        #pragma unroll
        for (int ni = 0; ni < NT8; ni++) {
            const int col = colbase + warp_n + ni * 8 + 2 * l;
            const float b0 = isInit ? bias1[col - 256] : bias0[col];
            const float b1 = isInit ? bias1[col - 255] : bias0[col + 1];
            #pragma unroll
            for (int hm = 0; hm < 2; hm++) {
                const int r = rowbase + warp_m + mi * 16 + g + hm * 8;
                if (r >= M) continue;
                float ox = leaky(c[mi][ni][hm * 2 + 0] + b0);
                float oy = leaky(c[mi][ni][hm * 2 + 1] + b1);
                __half2 h = __float22half2_rn(make_float2(ox, oy));
                if (isInit)
                    *reinterpret_cast<uint32_t*>(
                        a0h + (size_t)r * 64 + col - 256) =
                        *reinterpret_cast<uint32_t*>(&h);
                else
                    *reinterpret_cast<uint32_t*>(
                        resh + (size_t)r * 256 + col) =
                        *reinterpret_cast<uint32_t*>(&h);
            }
        }
    }
}

// ---------------------------------------------------------------------------
// FINAL GEMM: out = leaky(a2h @ wfT^T + b_fin) + resh.  CTAN=128, fp32 out.
// ---------------------------------------------------------------------------
__global__ __launch_bounds__(256, 2)
void hgemm_fin(const __half* __restrict__ A, const __half* __restrict__ Bt,
               const float* __restrict__ bias, const __half* __restrict__ resh,
               float* __restrict__ C, int M)
{
    constexpr int KD    = 256;
    constexpr int BK    = 64;
    constexpr int NST   = KD / BK;
    constexpr int CTAN  = 128;
    constexpr int ABY   = 128 * 128;
    constexpr int BBY   = CTAN * 128;
    constexpr int STAGE = ABY + BBY;
    constexpr int NT16  = CTAN / 32;         // 4
    constexpr int NT8   = 2 * NT16;          // 8

    extern __shared__ char smem[];
    const uint32_t sbase = (uint32_t)__cvta_generic_to_shared(smem);

    const int tid  = threadIdx.x;
    const int wid  = tid >> 5;
    const int lane = tid & 31;
    const int g = lane >> 2;
    const int l = lane & 3;
    const int quad = lane >> 3;
    const int lrow = lane & 7;
    const int warp_m = (wid & 3) * 32;
    const int warp_n = (wid >> 2) * (CTAN / 2);
    const int rowbase = blockIdx.x * 128;
    const int colbase = blockIdx.y * CTAN;

    const int pa_r = tid >> 3, pa_c = tid & 7;
    const int arow  = warp_m + (quad & 1) * 8 + lrow;
    const int ac_hi = quad >> 1;
    const int brow0 = warp_n + ((quad >> 1) & 1) * 8 + lrow;
    const int bc_lo = quad & 1;

    float c[2][NT8][4];
    #pragma unroll
    for (int mi = 0; mi < 2; mi++)
        #pragma unroll
        for (int ni = 0; ni < NT8; ni++)
            #pragma unroll
            for (int j = 0; j < 4; j++)
                c[mi][ni][j] = 0.0f;

    auto issue = [&](int t) {
        const int kk = t * BK;
        const uint32_t st = sbase + (t & 1) * STAGE;
        #pragma unroll
        for (int i = 0; i < 4; i++) {
            int r = pa_r + i * 32;
            int grow = rowbase + r;
            bool v = grow < M;
            const __half* src =
                A + (size_t)(v ? grow : 0) * KD + kk + pa_c * 8;
            uint32_t dst = st + r * 128 + ((pa_c ^ (r & 7)) << 4);
            cp_async16(dst, src, v ? 16u : 0u);
        }
        #pragma unroll
        for (int i = 0; i < 4; i++) {
            int r = pa_r + i * 32;
            const __half* src =
                Bt + (size_t)(colbase + r) * KD + kk + pa_c * 8;
            uint32_t dst = st + ABY + r * 128 + ((pa_c ^ (r & 7)) << 4);
            cp_async16(dst, src, 16u);
        }
        CP_COMMIT();
    };

    issue(0);
    issue(1);
    CP_WAIT(1);
    __syncthreads();

    for (int t = 0; t < NST; t++) {
        const uint32_t st = sbase + (t & 1) * STAGE;
        #pragma unroll
        for (int ks8 = 0; ks8 < BK / 8; ks8 += 2) {
            uint32_t af[2][4];
            #pragma unroll
            for (int mi = 0; mi < 2; mi++) {
                int r = arow + mi * 16;
                int cch = ks8 + ac_hi;
                uint32_t addr = st + r * 128 + ((cch ^ (r & 7)) << 4);
                LDSM_X4(af[mi][0], af[mi][1], af[mi][2], af[mi][3], addr);
            }
            uint32_t bf[NT16][4];
            #pragma unroll
            for (int nt = 0; nt < NT16; nt++) {
                int r = brow0 + nt * 16;
                int cch = ks8 + bc_lo;
                uint32_t addr = st + ABY + r * 128 + ((cch ^ (r & 7)) << 4);
                LDSM_X4(bf[nt][0], bf[nt][1], bf[nt][2], bf[nt][3], addr);
            }
            #pragma unroll
            for (int nt = 0; nt < NT16; nt++) {
                MMA_F16(c[0][nt * 2 + 0], af[0], bf[nt][0], bf[nt][1]);
                MMA_F16(c[1][nt * 2 + 0], af[1], bf[nt][0], bf[nt][1]);
                MMA_F16(c[0][nt * 2 + 1], af[0], bf[nt][2], bf[nt][3]);
                MMA_F16(c[1][nt * 2 + 1], af[1], bf[nt][2], bf[nt][3]);
            }
        }
        __syncthreads();
        if (t + 1 < NST) {
            if (t + 2 < NST) { issue(t + 2); CP_WAIT(1); }
            else             { CP_WAIT(0); }
            __syncthreads();
        }
    }

    // ---- epilogue: bias + leaky + half residual, fp32 stores ----
    #pragma unroll
    for (int mi = 0; mi < 2; mi++) {
        #pragma unroll
        for (int ni = 0; ni < NT8; ni++) {
            const int col = colbase + warp_n + ni * 8 + 2 * l;
            const float b0 = bias[col];
            const float b1 = bias[col + 1];
            #pragma unroll
            for (int hm = 0; hm < 2; hm++) {
                const int r = rowbase + warp_m + mi * 16 + g + hm * 8;
                if (r >= M) continue;
                uint32_t ru = *reinterpret_cast<const uint32_t*>(
                    resh + (size_t)r * 256 + col);
                float2 rv = __half22float2(*reinterpret_cast<__half2*>(&ru));
                float2 o;
                o.x = leaky(c[mi][ni][hm * 2 + 0] + b0) + rv.x;
                o.y = leaky(c[mi][ni][hm * 2 + 1] + b1) + rv.y;
                *reinterpret_cast<float2*>(C + (size_t)r * 256 + col) = o;
            }
        }
    }
}

// ---------------------------------------------------------------------------
// LFA (warp-per-point): feat HALF in, out HALF.
// ---------------------------------------------------------------------------
template <int D>
__global__ __launch_bounds__(256)
void lfa_half(const __half* __restrict__ feat,
              const float* __restrict__ geom,
              const int*   __restrict__ idx,
              const float* __restrict__ wg,
              const float* __restrict__ bg,
              __half* __restrict__ out, int N)
{
    constexpr int V = D / 32;
    __shared__ float gs[8][16][4];
    __shared__ int   is[8][16];

    const int tid  = threadIdx.x;
    const int wid  = tid >> 5;
    const int lane = tid & 31;
    const int pbase = blockIdx.x * 8;

    for (int i = tid; i < 8 * 64; i += 256) {
        int pp = pbase + (i >> 6);
        (&gs[0][0][0])[i] = (pp < N) ? geom[(size_t)pp * 64 + (i & 63)] : 0.f;
    }
    for (int i = tid; i < 8 * 16; i += 256) {
        int pp = pbase + (i >> 4);
        is[i >> 4][i & 15] = (pp < N) ? idx[(size_t)pp * 16 + (i & 15)] : 0;
    }
    __syncthreads();

    const int p = pbase + wid;
    if (p >= N) return;

    const int ch0 = lane * V;
    float w[4][V], bb[V];
    #pragma unroll
    for (int cc = 0; cc < V; cc++) {
        bb[cc] = bg[ch0 + cc];
        #pragma unroll
        for (int r = 0; r < 4; r++) w[r][cc] = wg[r * D + ch0 + cc];
    }

    float gsum[V], fsum[V];
    #pragma unroll
    for (int cc = 0; cc < V; cc++) { gsum[cc] = 0.f; fsum[cc] = 0.f; }

    #pragma unroll
    for (int k = 0; k < 16; k++) {
        const float g0 = gs[wid][k][0], g1 = gs[wid][k][1];
        const float g2 = gs[wid][k][2], g3 = gs[wid][k][3];
        const __half* fr = feat + (size_t)is[wid][k] * D + ch0;
        float fv[V];
        if constexpr (V == 4) {
            uint2 u = *reinterpret_cast<const uint2*>(fr);
            float2 f0 = __half22float2(*reinterpret_cast<__half2*>(&u.x));
            float2 f1 = __half22float2(*reinterpret_cast<__half2*>(&u.y));
            fv[0] = f0.x; fv[1] = f0.y; fv[2] = f1.x; fv[3] = f1.y;
        } else {
            uint32_t u = *reinterpret_cast<const uint32_t*>(fr);
            float2 f0 = __half22float2(*reinterpret_cast<__half2*>(&u));
            fv[0] = f0.x; fv[1] = f0.y;
        }
        #pragma unroll
        for (int cc = 0; cc < V; cc++) {
            float v = fmaf(g0, w[0][cc],
                      fmaf(g1, w[1][cc],
                      fmaf(g2, w[2][cc],
                      fmaf(g3, w[3][cc], bb[cc]))));
            gsum[cc] += leaky(v);
            fsum[cc] += fv[cc];
        }
    }

    __half* og = out + (size_t)p * (2 * D) + ch0;
    __half* of = og + D;
    if constexpr (V == 4) {
        __half2 h0 = __float22half2_rn(
            make_float2(gsum[0] * 0.0625f, gsum[1] * 0.0625f));
        __half2 h1 = __float22half2_rn(
            make_float2(gsum[2] * 0.0625f, gsum[3] * 0.0625f));
        uint2 u;
        u.x = *reinterpret_cast<uint32_t*>(&h0);
        u.y = *reinterpret_cast<uint32_t*>(&h1);
        *reinterpret_cast<uint2*>(og) = u;
        __half2 f0 = __float22half2_rn(
            make_float2(fsum[0] * 0.0625f, fsum[1] * 0.0625f));
        __half2 f1 = __float22half2_rn(
            make_float2(fsum[2] * 0.0625f, fsum[3] * 0.0625f));
        uint2 v;
        v.x = *reinterpret_cast<uint32_t*>(&f0);
        v.y = *reinterpret_cast<uint32_t*>(&f1);
        *reinterpret_cast<uint2*>(of) = v;
    } else {
        __half2 h0 = __float22half2_rn(
            make_float2(gsum[0] * 0.0625f, gsum[1] * 0.0625f));
        *reinterpret_cast<uint32_t*>(og) = *reinterpret_cast<uint32_t*>(&h0);
        __half2 f0 = __float22half2_rn(
            make_float2(fsum[0] * 0.0625f, fsum[1] * 0.0625f));
        *reinterpret_cast<uint32_t*>(of) = *reinterpret_cast<uint32_t*>(&f0);
    }
}

// ---------------------------------------------------------------------------
extern "C" void kernel_launch(void* const* d_in, const int* in_sizes, int n_in,
                              void* d_out, int out_size)
{
    const float* X      = (const float*)d_in[0];
    const float* geom   = (const float*)d_in[1];
    const int*   idx    = (const int*)  d_in[2];
    const float* w_res  = (const float*)d_in[3];
    const float* b_res  = (const float*)d_in[4];
    const float* w_init = (const float*)d_in[5];
    const float* b_init = (const float*)d_in[6];
    const float* w_g1   = (const float*)d_in[7];
    const float* b_g1   = (const float*)d_in[8];
    const float* w_g2   = (const float*)d_in[9];
    const float* b_g2   = (const float*)d_in[10];
    const float* w_fin  = (const float*)d_in[11];
    const float* b_fin  = (const float*)d_in[12];
    float* out = (float*)d_out;

    const int N = in_sizes[0] / DIM;

    __half *resh, *a0h, *a1h, *a2h, *wcat, *wfT;
    cudaGetSymbolAddress((void**)&resh, g_resh);
    cudaGetSymbolAddress((void**)&a0h,  g_a0h);
    cudaGetSymbolAddress((void**)&a1h,  g_a1h);
    cudaGetSymbolAddress((void**)&a2h,  g_a2h);
    cudaGetSymbolAddress((void**)&wcat, g_wcat);
    cudaGetSymbolAddress((void**)&wfT,  g_wfT);

    constexpr int SMEM_CAT   = 2 * (128 * 128 + 64 * 128);   // 48 KB
    constexpr int SMEM_FINAL = 2 * (128 * 128 + 128 * 128);  // 64 KB
    cudaFuncSetAttribute(hgemm_cat,
                         cudaFuncAttributeMaxDynamicSharedMemorySize, SMEM_CAT);
    cudaFuncSetAttribute(hgemm_fin,
                         cudaFuncAttributeMaxDynamicSharedMemorySize, SMEM_FINAL);

    const int gridM = (N + 127) / 128;

    // 0) weight prep (one launch)
    prep_all<<<144, dim3(32, 8)>>>(w_res, w_init, w_fin, wcat, wfT);
    // 1+2) fused: resh (half) + a0h (half) = leaky(X @ [w_res|w_init] + b)
    hgemm_cat<<<dim3(gridM, 5), 256, SMEM_CAT>>>(
        X, wcat, b_res, b_init, resh, a0h, N);
    // 3) a1 = LFA(a0)  [N,128] half
    lfa_half<64><<<(N + 7) / 8, 256>>>(a0h, geom, idx, w_g1, b_g1, a1h, N);
    // 4) a2 = LFA(a1)  [N,256] half
    lfa_half<128><<<(N + 7) / 8, 256>>>(a1h, geom, idx, w_g2, b_g2, a2h, N);
    // 5) out = leaky(a2 @ w_fin + b_fin) + resh
    hgemm_fin<<<dim3(gridM, 2), 256, SMEM_FINAL>>>(
        a2h, wfT, b_fin, resh, out, N);
}

// round 8
// speedup vs baseline: 3.3876x; 1.0557x over previous
#include <cuda_runtime.h>
#include <cuda_fp16.h>
#include <cstdint>

#define NPTS 50000
#define DIM 256

// ---------------- scratch (no-alloc rule: __device__ globals) --------------
__device__ __half g_resh[NPTS * DIM];       // residual, half
__device__ __half g_a0h[NPTS * (DIM / 4)];  // init MLP out, half
__device__ __half g_a1h[NPTS * (DIM / 2)];  // LFA1 out, half
__device__ __half g_a2h[NPTS * DIM];        // LFA2 out, half
__device__ __half g_wcat[(DIM + DIM / 4) * DIM]; // [w_res^T ; w_init^T] [320,256]
__device__ __half g_wfT[DIM * DIM];         // w_fin^T half [256,256]

__device__ __forceinline__ float leaky(float x) {
    return x >= 0.0f ? x : 0.2f * x;
}

#define MMA_F16(c, a, b0, b1)                                             \
    asm volatile(                                                         \
        "mma.sync.aligned.m16n8k16.row.col.f32.f16.f16.f32 "              \
        "{%0,%1,%2,%3}, {%4,%5,%6,%7}, {%8,%9}, {%0,%1,%2,%3};"           \
        : "+f"((c)[0]), "+f"((c)[1]), "+f"((c)[2]), "+f"((c)[3])          \
        : "r"((a)[0]), "r"((a)[1]), "r"((a)[2]), "r"((a)[3]),             \
          "r"(b0), "r"(b1))

#define LDSM_X4(r0, r1, r2, r3, addr)                                     \
    asm volatile(                                                         \
        "ldmatrix.sync.aligned.m8n8.x4.shared.b16 {%0,%1,%2,%3}, [%4];"   \
        : "=r"(r0), "=r"(r1), "=r"(r2), "=r"(r3) : "r"(addr))

__device__ __forceinline__ void cp_async16(uint32_t dst, const void* src,
                                           uint32_t src_bytes) {
    asm volatile("cp.async.ca.shared.global [%0], [%1], 16, %2;"
                 :: "r"(dst), "l"(src), "r"(src_bytes));
}
#define CP_COMMIT() asm volatile("cp.async.commit_group;")
#define CP_WAIT(n)  asm volatile("cp.async.wait_group %0;" :: "n"(n))

// ---------------------------------------------------------------------------
// Merged weight prep: fp32 [K,N] -> half [N,K] for all 3 GEMM weights.
// ---------------------------------------------------------------------------
__global__ void prep_all(const float* __restrict__ w_res,
                         const float* __restrict__ w_init,
                         const float* __restrict__ w_fin,
                         __half* __restrict__ wcat,
                         __half* __restrict__ wfT)
{
    __shared__ float t[32][33];
    const float* in;
    __half* out;
    int K = 256, N, bx;
    if (blockIdx.x < 64)      { in = w_res;  out = wcat; N = 256; bx = blockIdx.x; }
    else if (blockIdx.x < 80) { in = w_init; out = wcat + 256 * 256; N = 64;
                                bx = blockIdx.x - 64; }
    else                      { in = w_fin;  out = wfT;  N = 256; bx = blockIdx.x - 80; }
    int nTx = N / 32;
    int n0 = (bx % nTx) * 32;
    int k0 = (bx / nTx) * 32;
    for (int i = threadIdx.y; i < 32; i += 8)
        t[i][threadIdx.x] = in[(size_t)(k0 + i) * N + n0 + threadIdx.x];
    __syncthreads();
    for (int i = threadIdx.y; i < 32; i += 8)
        out[(size_t)(n0 + i) * K + k0 + threadIdx.x] =
            __float2half(t[threadIdx.x][i]);
}

// ---------------------------------------------------------------------------
// CAT GEMM (fused stage 1+2): A = X fp32 [M,256] (inline cvt at STS),
// B = wcat half [320,256] k-major.  CTAN=64, grid.y=5 (cols 0..319).
// ---------------------------------------------------------------------------
__global__ __launch_bounds__(256, 2)
void hgemm_cat(const float* __restrict__ A, const __half* __restrict__ Bt,
               const float* __restrict__ bias0, const float* __restrict__ bias1,
               __half* __restrict__ resh, __half* __restrict__ a0h, int M)
{
    constexpr int KD    = 256;
    constexpr int BK    = 64;
    constexpr int NST   = KD / BK;           // 4
    constexpr int CTAN  = 64;
    constexpr int ABY   = 128 * 128;
    constexpr int BBY   = CTAN * 128;
    constexpr int STAGE = ABY + BBY;
    constexpr int NT16  = CTAN / 32;         // 2
    constexpr int NT8   = 2 * NT16;          // 4

    extern __shared__ char smem[];
    const uint32_t sbase = (uint32_t)__cvta_generic_to_shared(smem);

    const int tid  = threadIdx.x;
    const int wid  = tid >> 5;
    const int lane = tid & 31;
    const int g = lane >> 2;
    const int l = lane & 3;
    const int quad = lane >> 3;
    const int lrow = lane & 7;
    const int warp_m = (wid & 3) * 32;
    const int warp_n = (wid >> 2) * (CTAN / 2);
    const int rowbase = blockIdx.x * 128;
    const int colbase = blockIdx.y * CTAN;

    const int pa_r = tid >> 3, pa_c = tid & 7;

    const int arow  = warp_m + (quad & 1) * 8 + lrow;
    const int ac_hi = quad >> 1;
    const int brow0 = warp_n + ((quad >> 1) & 1) * 8 + lrow;
    const int bc_lo = quad & 1;

    float c[2][NT8][4];
    #pragma unroll
    for (int mi = 0; mi < 2; mi++)
        #pragma unroll
        for (int ni = 0; ni < NT8; ni++)
            #pragma unroll
            for (int j = 0; j < 4; j++)
                c[mi][ni][j] = 0.0f;

    float4 aR[4][2];

    auto ldgA = [&](int t) {
        const int kk = t * BK;
        #pragma unroll
        for (int i = 0; i < 4; i++) {
            int r = pa_r + i * 32;
            int grow = rowbase + r;
            if (grow < M) {
                const float4* src = reinterpret_cast<const float4*>(
                    A + (size_t)grow * KD + kk + pa_c * 8);
                aR[i][0] = src[0];
                aR[i][1] = src[1];
            } else {
                aR[i][0] = make_float4(0.f, 0.f, 0.f, 0.f);
                aR[i][1] = make_float4(0.f, 0.f, 0.f, 0.f);
            }
        }
    };

    auto storeA = [&](int t) {
        const uint32_t st = sbase + (t & 1) * STAGE;
        #pragma unroll
        for (int i = 0; i < 4; i++) {
            int r = pa_r + i * 32;
            __half2 h0 = __float22half2_rn(make_float2(aR[i][0].x, aR[i][0].y));
            __half2 h1 = __float22half2_rn(make_float2(aR[i][0].z, aR[i][0].w));
            __half2 h2 = __float22half2_rn(make_float2(aR[i][1].x, aR[i][1].y));
            __half2 h3 = __float22half2_rn(make_float2(aR[i][1].z, aR[i][1].w));
            uint4 v;
            v.x = *reinterpret_cast<uint32_t*>(&h0);
            v.y = *reinterpret_cast<uint32_t*>(&h1);
            v.z = *reinterpret_cast<uint32_t*>(&h2);
            v.w = *reinterpret_cast<uint32_t*>(&h3);
            uint32_t dst = st + r * 128 + ((pa_c ^ (r & 7)) << 4);
            *reinterpret_cast<uint4*>(smem + (dst - sbase)) = v;
        }
    };

    auto issueB = [&](int t) {
        const int kk = t * BK;
        const uint32_t st = sbase + (t & 1) * STAGE;
        #pragma unroll
        for (int i = 0; i < 2; i++) {
            int r = pa_r + i * 32;
            const __half* src =
                Bt + (size_t)(colbase + r) * KD + kk + pa_c * 8;
            uint32_t dst = st + ABY + r * 128 + ((pa_c ^ (r & 7)) << 4);
            cp_async16(dst, src, 16u);
        }
        CP_COMMIT();
    };

    ldgA(0);
    issueB(0);
    issueB(1);
    storeA(0);
    CP_WAIT(1);
    __syncthreads();

    for (int t = 0; t < NST; t++) {
        const uint32_t st = sbase + (t & 1) * STAGE;
        if (t + 1 < NST) ldgA(t + 1);

        #pragma unroll
        for (int ks8 = 0; ks8 < BK / 8; ks8 += 2) {
            uint32_t af[2][4];
            #pragma unroll
            for (int mi = 0; mi < 2; mi++) {
                int r = arow + mi * 16;
                int cch = ks8 + ac_hi;
                uint32_t addr = st + r * 128 + ((cch ^ (r & 7)) << 4);
                LDSM_X4(af[mi][0], af[mi][1], af[mi][2], af[mi][3], addr);
            }
            uint32_t bf[NT16][4];
            #pragma unroll
            for (int nt = 0; nt < NT16; nt++) {
                int r = brow0 + nt * 16;
                int cch = ks8 + bc_lo;
                uint32_t addr = st + ABY + r * 128 + ((cch ^ (r & 7)) << 4);
                LDSM_X4(bf[nt][0], bf[nt][1], bf[nt][2], bf[nt][3], addr);
            }
            #pragma unroll
            for (int nt = 0; nt < NT16; nt++) {
                MMA_F16(c[0][nt * 2 + 0], af[0], bf[nt][0], bf[nt][1]);
                MMA_F16(c[1][nt * 2 + 0], af[1], bf[nt][0], bf[nt][1]);
                MMA_F16(c[0][nt * 2 + 1], af[0], bf[nt][2], bf[nt][3]);
                MMA_F16(c[1][nt * 2 + 1], af[1], bf[nt][2], bf[nt][3]);
            }
        }
        __syncthreads();
        if (t + 1 < NST) {
            storeA(t + 1);
            if (t + 2 < NST) { issueB(t + 2); CP_WAIT(1); }
            else             { CP_WAIT(0); }
            __syncthreads();
        }
    }

    const bool isInit = (colbase >= 256);
    #pragma unroll
    for (int mi = 0; mi < 2; mi++) {
        #pragma unroll
        for (int ni = 0; ni < NT8; ni++) {
            const int col = colbase + warp_n + ni * 8 + 2 * l;
            const float b0 = isInit ? bias1[col - 256] : bias0[col];
            const float b1 = isInit ? bias1[col - 255] : bias0[col + 1];
            #pragma unroll
            for (int hm = 0; hm < 2; hm++) {
                const int r = rowbase + warp_m + mi * 16 + g + hm * 8;
                if (r >= M) continue;
                float ox = leaky(c[mi][ni][hm * 2 + 0] + b0);
                float oy = leaky(c[mi][ni][hm * 2 + 1] + b1);
                __half2 h = __float22half2_rn(make_float2(ox, oy));
                if (isInit)
                    *reinterpret_cast<uint32_t*>(
                        a0h + (size_t)r * 64 + col - 256) =
                        *reinterpret_cast<uint32_t*>(&h);
                else
                    *reinterpret_cast<uint32_t*>(
                        resh + (size_t)r * 256 + col) =
                        *reinterpret_cast<uint32_t*>(&h);
            }
        }
    }
}

// ---------------------------------------------------------------------------
// FINAL GEMM: out = leaky(a2h @ wfT^T + b_fin) + resh.  CTAN=128, fp32 out.
// ---------------------------------------------------------------------------
__global__ __launch_bounds__(256, 2)
void hgemm_fin(const __half* __restrict__ A, const __half* __restrict__ Bt,
               const float* __restrict__ bias, const __half* __restrict__ resh,
               float* __restrict__ C, int M)
{
    constexpr int KD    = 256;
    constexpr int BK    = 64;
    constexpr int NST   = KD / BK;
    constexpr int CTAN  = 128;
    constexpr int ABY   = 128 * 128;
    constexpr int BBY   = CTAN * 128;
    constexpr int STAGE = ABY + BBY;
    constexpr int NT16  = CTAN / 32;         // 4
    constexpr int NT8   = 2 * NT16;          // 8

    extern __shared__ char smem[];
    const uint32_t sbase = (uint32_t)__cvta_generic_to_shared(smem);

    const int tid  = threadIdx.x;
    const int wid  = tid >> 5;
    const int lane = tid & 31;
    const int g = lane >> 2;
    const int l = lane & 3;
    const int quad = lane >> 3;
    const int lrow = lane & 7;
    const int warp_m = (wid & 3) * 32;
    const int warp_n = (wid >> 2) * (CTAN / 2);
    const int rowbase = blockIdx.x * 128;
    const int colbase = blockIdx.y * CTAN;

    const int pa_r = tid >> 3, pa_c = tid & 7;
    const int arow  = warp_m + (quad & 1) * 8 + lrow;
    const int ac_hi = quad >> 1;
    const int brow0 = warp_n + ((quad >> 1) & 1) * 8 + lrow;
    const int bc_lo = quad & 1;

    float c[2][NT8][4];
    #pragma unroll
    for (int mi = 0; mi < 2; mi++)
        #pragma unroll
        for (int ni = 0; ni < NT8; ni++)
            #pragma unroll
            for (int j = 0; j < 4; j++)
                c[mi][ni][j] = 0.0f;

    auto issue = [&](int t) {
        const int kk = t * BK;
        const uint32_t st = sbase + (t & 1) * STAGE;
        #pragma unroll
        for (int i = 0; i < 4; i++) {
            int r = pa_r + i * 32;
            int grow = rowbase + r;
            bool v = grow < M;
            const __half* src =
                A + (size_t)(v ? grow : 0) * KD + kk + pa_c * 8;
            uint32_t dst = st + r * 128 + ((pa_c ^ (r & 7)) << 4);
            cp_async16(dst, src, v ? 16u : 0u);
        }
        #pragma unroll
        for (int i = 0; i < 4; i++) {
            int r = pa_r + i * 32;
            const __half* src =
                Bt + (size_t)(colbase + r) * KD + kk + pa_c * 8;
            uint32_t dst = st + ABY + r * 128 + ((pa_c ^ (r & 7)) << 4);
            cp_async16(dst, src, 16u);
        }
        CP_COMMIT();
    };

    issue(0);
    issue(1);
    CP_WAIT(1);
    __syncthreads();

    for (int t = 0; t < NST; t++) {
        const uint32_t st = sbase + (t & 1) * STAGE;
        #pragma unroll
        for (int ks8 = 0; ks8 < BK / 8; ks8 += 2) {
            uint32_t af[2][4];
            #pragma unroll
            for (int mi = 0; mi < 2; mi++) {
                int r = arow + mi * 16;
                int cch = ks8 + ac_hi;
                uint32_t addr = st + r * 128 + ((cch ^ (r & 7)) << 4);
                LDSM_X4(af[mi][0], af[mi][1], af[mi][2], af[mi][3], addr);
            }
            uint32_t bf[NT16][4];
            #pragma unroll
            for (int nt = 0; nt < NT16; nt++) {
                int r = brow0 + nt * 16;
                int cch = ks8 + bc_lo;
                uint32_t addr = st + ABY + r * 128 + ((cch ^ (r & 7)) << 4);
                LDSM_X4(bf[nt][0], bf[nt][1], bf[nt][2], bf[nt][3], addr);
            }
            #pragma unroll
            for (int nt = 0; nt < NT16; nt++) {
                MMA_F16(c[0][nt * 2 + 0], af[0], bf[nt][0], bf[nt][1]);
                MMA_F16(c[1][nt * 2 + 0], af[1], bf[nt][0], bf[nt][1]);
                MMA_F16(c[0][nt * 2 + 1], af[0], bf[nt][2], bf[nt][3]);
                MMA_F16(c[1][nt * 2 + 1], af[1], bf[nt][2], bf[nt][3]);
            }
        }
        __syncthreads();
        if (t + 1 < NST) {
            if (t + 2 < NST) { issue(t + 2); CP_WAIT(1); }
            else             { CP_WAIT(0); }
            __syncthreads();
        }
    }

    #pragma unroll
    for (int mi = 0; mi < 2; mi++) {
        #pragma unroll
        for (int ni = 0; ni < NT8; ni++) {
            const int col = colbase + warp_n + ni * 8 + 2 * l;
            const float b0 = bias[col];
            const float b1 = bias[col + 1];
            #pragma unroll
            for (int hm = 0; hm < 2; hm++) {
                const int r = rowbase + warp_m + mi * 16 + g + hm * 8;
                if (r >= M) continue;
                uint32_t ru = *reinterpret_cast<const uint32_t*>(
                    resh + (size_t)r * 256 + col);
                float2 rv = __half22float2(*reinterpret_cast<__half2*>(&ru));
                float2 o;
                o.x = leaky(c[mi][ni][hm * 2 + 0] + b0) + rv.x;
                o.y = leaky(c[mi][ni][hm * 2 + 1] + b1) + rv.y;
                *reinterpret_cast<float2*>(C + (size_t)r * 256 + col) = o;
            }
        }
    }
}

// ---------------------------------------------------------------------------
// geom_mlp: computes BOTH geometry-MLP means in one pass (depends only on geom)
//   a1h[p, 0:64]   = mean_k leaky(geom[p,k]@Wg1 + b1)
//   a2h[p, 0:128]  = mean_k leaky(geom[p,k]@Wg2 + b2)
// 8 points/CTA, warp per point, lane = 6 channels (3 half2 pairs) of the
// 192 concatenated channels. half2 HFMA2 affine, fp32 mean accumulation.
// ---------------------------------------------------------------------------
__global__ __launch_bounds__(256)
void geom_mlp(const float* __restrict__ geom,
              const float* __restrict__ wg1, const float* __restrict__ bg1,
              const float* __restrict__ wg2, const float* __restrict__ bg2,
              __half* __restrict__ a1h, __half* __restrict__ a2h, int N)
{
    __shared__ uint2 gsm[8][16];   // per (pt,k): (half2(g0,g1), half2(g2,g3))

    const int tid  = threadIdx.x;
    const int wid  = tid >> 5;
    const int lane = tid & 31;
    const int pbase = blockIdx.x * 8;

    if (tid < 128) {
        int pp = pbase + (tid >> 4);
        int k  = tid & 15;
        float4 gv = (pp < N)
            ? reinterpret_cast<const float4*>(geom)[(size_t)pp * 16 + k]
            : make_float4(0.f, 0.f, 0.f, 0.f);
        __half2 g01 = __float22half2_rn(make_float2(gv.x, gv.y));
        __half2 g23 = __float22half2_rn(make_float2(gv.z, gv.w));
        uint2 u;
        u.x = *reinterpret_cast<uint32_t*>(&g01);
        u.y = *reinterpret_cast<uint32_t*>(&g23);
        gsm[tid >> 4][k] = u;
    }
    __syncthreads();

    const int p = pbase + wid;
    if (p >= N) return;

    const int ch0 = lane * 6;
    __half2 w0[3], w1[3], w2[3], w3[3], bb[3];
    #pragma unroll
    for (int j = 0; j < 3; j++) {
        int ch = ch0 + 2 * j;
        const float* wsrc;
        const float* bsrc;
        int str, cb;
        if (ch < 64) { wsrc = wg1; bsrc = bg1; str = 64;  cb = ch; }
        else         { wsrc = wg2; bsrc = bg2; str = 128; cb = ch - 64; }
        w0[j] = __floats2half2_rn(wsrc[0 * str + cb], wsrc[0 * str + cb + 1]);
        w1[j] = __floats2half2_rn(wsrc[1 * str + cb], wsrc[1 * str + cb + 1]);
        w2[j] = __floats2half2_rn(wsrc[2 * str + cb], wsrc[2 * str + cb + 1]);
        w3[j] = __floats2half2_rn(wsrc[3 * str + cb], wsrc[3 * str + cb + 1]);
        bb[j] = __floats2half2_rn(bsrc[cb], bsrc[cb + 1]);
    }

    const __half2 zero = __float2half2_rn(0.0f);
    const __half2 p02  = __float2half2_rn(0.2f);
    float acc[6];
    #pragma unroll
    for (int i = 0; i < 6; i++) acc[i] = 0.0f;

    #pragma unroll
    for (int k = 0; k < 16; k++) {
        uint2 u = gsm[wid][k];
        __half2 g01 = *reinterpret_cast<__half2*>(&u.x);
        __half2 g23 = *reinterpret_cast<__half2*>(&u.y);
        __half2 gb0 = __low2half2(g01);
        __half2 gb1 = __high2half2(g01);
        __half2 gb2 = __low2half2(g23);
        __half2 gb3 = __high2half2(g23);
        #pragma unroll
        for (int j = 0; j < 3; j++) {
            __half2 v = bb[j];
            v = __hfma2(gb0, w0[j], v);
            v = __hfma2(gb1, w1[j], v);
            v = __hfma2(gb2, w2[j], v);
            v = __hfma2(gb3, w3[j], v);
            __half2 lk = __hfma2(__hmin2(v, zero), p02, __hmax2(v, zero));
            float2 f = __half22float2(lk);
            acc[2 * j]     += f.x;
            acc[2 * j + 1] += f.y;
        }
    }

    #pragma unroll
    for (int j = 0; j < 3; j++) {
        int ch = ch0 + 2 * j;
        __half2 o = __float22half2_rn(
            make_float2(acc[2 * j] * 0.0625f, acc[2 * j + 1] * 0.0625f));
        if (ch < 64)
            *reinterpret_cast<uint32_t*>(a1h + (size_t)p * 128 + ch) =
                *reinterpret_cast<uint32_t*>(&o);
        else
            *reinterpret_cast<uint32_t*>(a2h + (size_t)p * 256 + (ch - 64)) =
                *reinterpret_cast<uint32_t*>(&o);
    }
}

// ---------------------------------------------------------------------------
// gather1: a1h[p, 64:128] = mean_k a0h[idx[p,k], 0:64]  (warp/point, lane=uint)
// ---------------------------------------------------------------------------
__global__ __launch_bounds__(256)
void gather1(const __half* __restrict__ a0h, const int* __restrict__ idx,
             __half* __restrict__ a1h, int N)
{
    __shared__ int is[8][16];
    const int tid  = threadIdx.x;
    const int wid  = tid >> 5;
    const int lane = tid & 31;
    const int pbase = blockIdx.x * 8;

    if (tid < 128) {
        int pp = pbase + (tid >> 4);
        is[tid >> 4][tid & 15] =
            (pp < N) ? idx[(size_t)pp * 16 + (tid & 15)] : 0;
    }
    __syncthreads();

    const int p = pbase + wid;
    if (p >= N) return;

    const uint32_t* src = reinterpret_cast<const uint32_t*>(a0h);
    float sx = 0.f, sy = 0.f;
    #pragma unroll
    for (int k = 0; k < 16; k++) {
        uint32_t u = src[(size_t)is[wid][k] * 32 + lane];
        float2 f = __half22float2(*reinterpret_cast<__half2*>(&u));
        sx += f.x; sy += f.y;
    }
    __half2 o = __float22half2_rn(make_float2(sx * 0.0625f, sy * 0.0625f));
    *reinterpret_cast<uint32_t*>(a1h + (size_t)p * 128 + 64 + 2 * lane) =
        *reinterpret_cast<uint32_t*>(&o);
}

// ---------------------------------------------------------------------------
// gather2: a2h[p, 128:256] = mean_k a1h[idx[p,k], 0:128] (warp/point, lane=uint2)
// ---------------------------------------------------------------------------
__global__ __launch_bounds__(256)
void gather2(const __half* __restrict__ a1h, const int* __restrict__ idx,
             __half* __restrict__ a2h, int N)
{
    __shared__ int is[8][16];
    const int tid  = threadIdx.x;
    const int wid  = tid >> 5;
    const int lane = tid & 31;
    const int pbase = blockIdx.x * 8;

    if (tid < 128) {
        int pp = pbase + (tid >> 4);
        is[tid >> 4][tid & 15] =
            (pp < N) ? idx[(size_t)pp * 16 + (tid & 15)] : 0;
    }
    __syncthreads();

    const int p = pbase + wid;
    if (p >= N) return;

    const uint2* src = reinterpret_cast<const uint2*>(a1h);
    float s0 = 0.f, s1 = 0.f, s2 = 0.f, s3 = 0.f;
    #pragma unroll
    for (int k = 0; k < 16; k++) {
        uint2 u = src[(size_t)is[wid][k] * 32 + lane];
        float2 f0 = __half22float2(*reinterpret_cast<__half2*>(&u.x));
        float2 f1 = __half22float2(*reinterpret_cast<__half2*>(&u.y));
        s0 += f0.x; s1 += f0.y; s2 += f1.x; s3 += f1.y;
    }
    __half2 o0 = __float22half2_rn(make_float2(s0 * 0.0625f, s1 * 0.0625f));
    __half2 o1 = __float22half2_rn(make_float2(s2 * 0.0625f, s3 * 0.0625f));
    uint2 o;
    o.x = *reinterpret_cast<uint32_t*>(&o0);
    o.y = *reinterpret_cast<uint32_t*>(&o1);
    *reinterpret_cast<uint2*>(a2h + (size_t)p * 256 + 128 + 4 * lane) = o;
}

// ---------------------------------------------------------------------------
extern "C" void kernel_launch(void* const* d_in, const int* in_sizes, int n_in,
                              void* d_out, int out_size)
{
    const float* X      = (const float*)d_in[0];
    const float* geom   = (const float*)d_in[1];
    const int*   idx    = (const int*)  d_in[2];
    const float* w_res  = (const float*)d_in[3];
    const float* b_res  = (const float*)d_in[4];
    const float* w_init = (const float*)d_in[5];
    const float* b_init = (const float*)d_in[6];
    const float* w_g1   = (const float*)d_in[7];
    const float* b_g1   = (const float*)d_in[8];
    const float* w_g2   = (const float*)d_in[9];
    const float* b_g2   = (const float*)d_in[10];
    const float* w_fin  = (const float*)d_in[11];
    const float* b_fin  = (const float*)d_in[12];
    float* out = (float*)d_out;

    const int N = in_sizes[0] / DIM;

    __half *resh, *a0h, *a1h, *a2h, *wcat, *wfT;
    cudaGetSymbolAddress((void**)&resh, g_resh);
    cudaGetSymbolAddress((void**)&a0h,  g_a0h);
    cudaGetSymbolAddress((void**)&a1h,  g_a1h);
    cudaGetSymbolAddress((void**)&a2h,  g_a2h);
    cudaGetSymbolAddress((void**)&wcat, g_wcat);
    cudaGetSymbolAddress((void**)&wfT,  g_wfT);

    constexpr int SMEM_CAT   = 2 * (128 * 128 + 64 * 128);   // 48 KB
    constexpr int SMEM_FINAL = 2 * (128 * 128 + 128 * 128);  // 64 KB
    cudaFuncSetAttribute(hgemm_cat,
                         cudaFuncAttributeMaxDynamicSharedMemorySize, SMEM_CAT);
    cudaFuncSetAttribute(hgemm_fin,
                         cudaFuncAttributeMaxDynamicSharedMemorySize, SMEM_FINAL);

    const int gridM = (N + 127) / 128;
    const int gridP = (N + 7) / 8;

    // 0) weight prep
    prep_all<<<144, dim3(32, 8)>>>(w_res, w_init, w_fin, wcat, wfT);
    // 0b) geometry MLP halves of both LFA layers (independent of GEMMs)
    geom_mlp<<<gridP, 256>>>(geom, w_g1, b_g1, w_g2, b_g2, a1h, a2h, N);
    // 1+2) fused: resh (half) + a0h (half) = leaky(X @ [w_res|w_init] + b)
    hgemm_cat<<<dim3(gridM, 5), 256, SMEM_CAT>>>(
        X, wcat, b_res, b_init, resh, a0h, N);
    // 3) gather half of LFA1
    gather1<<<gridP, 256>>>(a0h, idx, a1h, N);
    // 4) gather half of LFA2
    gather2<<<gridP, 256>>>(a1h, idx, a2h, N);
    // 5) out = leaky(a2 @ w_fin + b_fin) + resh
    hgemm_fin<<<dim3(gridM, 2), 256, SMEM_FINAL>>>(
        a2h, wfT, b_fin, resh, out, N);
}

// round 9
// speedup vs baseline: 3.6665x; 1.0824x over previous
#include <cuda_runtime.h>
#include <cuda_fp16.h>
#include <cstdint>

#define NPTS 50000
#define DIM 256

// ---------------- scratch (no-alloc rule: __device__ globals) --------------
__device__ __half g_resh[NPTS * DIM];       // residual, half
__device__ __half g_a0h[NPTS * (DIM / 4)];  // init MLP out, half
__device__ __half g_a1h[NPTS * (DIM / 2)];  // LFA1 out, half
__device__ __half g_a2h[NPTS * DIM];        // LFA2 out, half
__device__ __half g_wcat[(DIM + DIM / 4) * DIM]; // [w_res^T ; w_init^T] [320,256]
__device__ __half g_wfT[DIM * DIM];         // w_fin^T half [256,256]

__device__ __forceinline__ float leaky(float x) {
    return x >= 0.0f ? x : 0.2f * x;
}

#define MMA_F16(c, a, b0, b1)                                             \
    asm volatile(                                                         \
        "mma.sync.aligned.m16n8k16.row.col.f32.f16.f16.f32 "              \
        "{%0,%1,%2,%3}, {%4,%5,%6,%7}, {%8,%9}, {%0,%1,%2,%3};"           \
        : "+f"((c)[0]), "+f"((c)[1]), "+f"((c)[2]), "+f"((c)[3])          \
        : "r"((a)[0]), "r"((a)[1]), "r"((a)[2]), "r"((a)[3]),             \
          "r"(b0), "r"(b1))

#define LDSM_X4(r0, r1, r2, r3, addr)                                     \
    asm volatile(                                                         \
        "ldmatrix.sync.aligned.m8n8.x4.shared.b16 {%0,%1,%2,%3}, [%4];"   \
        : "=r"(r0), "=r"(r1), "=r"(r2), "=r"(r3) : "r"(addr))

__device__ __forceinline__ void cp_async16(uint32_t dst, const void* src,
                                           uint32_t src_bytes) {
    asm volatile("cp.async.ca.shared.global [%0], [%1], 16, %2;"
                 :: "r"(dst), "l"(src), "r"(src_bytes));
}
#define CP_COMMIT() asm volatile("cp.async.commit_group;")
#define CP_WAIT(n)  asm volatile("cp.async.wait_group %0;" :: "n"(n))

// ---------------------------------------------------------------------------
// prep_geom: blocks [0,144) do weight prep; blocks [144,...) do geometry MLP.
// ---------------------------------------------------------------------------
__global__ __launch_bounds__(256)
void prep_geom(const float* __restrict__ w_res,
               const float* __restrict__ w_init,
               const float* __restrict__ w_fin,
               __half* __restrict__ wcat, __half* __restrict__ wfT,
               const float* __restrict__ geom,
               const float* __restrict__ wg1, const float* __restrict__ bg1,
               const float* __restrict__ wg2, const float* __restrict__ bg2,
               __half* __restrict__ a1h, __half* __restrict__ a2h, int N)
{
    const int tid = threadIdx.x;

    if (blockIdx.x < 144) {
        // ---------------- weight prep ----------------
        __shared__ float t[32][33];
        const float* in;
        __half* out;
        int K = 256, Nc, bx;
        if (blockIdx.x < 64)      { in = w_res;  out = wcat; Nc = 256; bx = blockIdx.x; }
        else if (blockIdx.x < 80) { in = w_init; out = wcat + 256 * 256; Nc = 64;
                                    bx = blockIdx.x - 64; }
        else                      { in = w_fin;  out = wfT;  Nc = 256; bx = blockIdx.x - 80; }
        int tx = tid & 31, ty = tid >> 5;
        int nTx = Nc / 32;
        int n0 = (bx % nTx) * 32;
        int k0 = (bx / nTx) * 32;
        for (int i = ty; i < 32; i += 8)
            t[i][tx] = in[(size_t)(k0 + i) * Nc + n0 + tx];
        __syncthreads();
        for (int i = ty; i < 32; i += 8)
            out[(size_t)(n0 + i) * K + k0 + tx] = __float2half(t[tx][i]);
        return;
    }

    // ---------------- geometry MLP (both layers) ----------------
    __shared__ uint2 gsm[8][16];
    const int wid  = tid >> 5;
    const int lane = tid & 31;
    const int pbase = (blockIdx.x - 144) * 8;

    if (tid < 128) {
        int pp = pbase + (tid >> 4);
        int k  = tid & 15;
        float4 gv = (pp < N)
            ? reinterpret_cast<const float4*>(geom)[(size_t)pp * 16 + k]
            : make_float4(0.f, 0.f, 0.f, 0.f);
        __half2 g01 = __float22half2_rn(make_float2(gv.x, gv.y));
        __half2 g23 = __float22half2_rn(make_float2(gv.z, gv.w));
        uint2 u;
        u.x = *reinterpret_cast<uint32_t*>(&g01);
        u.y = *reinterpret_cast<uint32_t*>(&g23);
        gsm[tid >> 4][k] = u;
    }
    __syncthreads();

    const int p = pbase + wid;
    if (p >= N) return;

    const int ch0 = lane * 6;
    __half2 w0[3], w1[3], w2[3], w3[3], bb[3];
    #pragma unroll
    for (int j = 0; j < 3; j++) {
        int ch = ch0 + 2 * j;
        const float* wsrc;
        const float* bsrc;
        int str, cb;
        if (ch < 64) { wsrc = wg1; bsrc = bg1; str = 64;  cb = ch; }
        else         { wsrc = wg2; bsrc = bg2; str = 128; cb = ch - 64; }
        w0[j] = __floats2half2_rn(wsrc[0 * str + cb], wsrc[0 * str + cb + 1]);
        w1[j] = __floats2half2_rn(wsrc[1 * str + cb], wsrc[1 * str + cb + 1]);
        w2[j] = __floats2half2_rn(wsrc[2 * str + cb], wsrc[2 * str + cb + 1]);
        w3[j] = __floats2half2_rn(wsrc[3 * str + cb], wsrc[3 * str + cb + 1]);
        bb[j] = __floats2half2_rn(bsrc[cb], bsrc[cb + 1]);
    }

    const __half2 zero = __float2half2_rn(0.0f);
    const __half2 p02  = __float2half2_rn(0.2f);
    float acc[6];
    #pragma unroll
    for (int i = 0; i < 6; i++) acc[i] = 0.0f;

    #pragma unroll
    for (int k = 0; k < 16; k++) {
        uint2 u = gsm[wid][k];
        __half2 g01 = *reinterpret_cast<__half2*>(&u.x);
        __half2 g23 = *reinterpret_cast<__half2*>(&u.y);
        __half2 gb0 = __low2half2(g01);
        __half2 gb1 = __high2half2(g01);
        __half2 gb2 = __low2half2(g23);
        __half2 gb3 = __high2half2(g23);
        #pragma unroll
        for (int j = 0; j < 3; j++) {
            __half2 v = bb[j];
            v = __hfma2(gb0, w0[j], v);
            v = __hfma2(gb1, w1[j], v);
            v = __hfma2(gb2, w2[j], v);
            v = __hfma2(gb3, w3[j], v);
            __half2 lk = __hfma2(__hmin2(v, zero), p02, __hmax2(v, zero));
            float2 f = __half22float2(lk);
            acc[2 * j]     += f.x;
            acc[2 * j + 1] += f.y;
        }
    }

    #pragma unroll
    for (int j = 0; j < 3; j++) {
        int ch = ch0 + 2 * j;
        __half2 o = __float22half2_rn(
            make_float2(acc[2 * j] * 0.0625f, acc[2 * j + 1] * 0.0625f));
        if (ch < 64)
            *reinterpret_cast<uint32_t*>(a1h + (size_t)p * 128 + ch) =
                *reinterpret_cast<uint32_t*>(&o);
        else
            *reinterpret_cast<uint32_t*>(a2h + (size_t)p * 256 + (ch - 64)) =
                *reinterpret_cast<uint32_t*>(&o);
    }
}

// ---------------------------------------------------------------------------
// CAT GEMM (fused stage 1+2): CTA tile 64 x 160, grid.y = 2 (cols 0..319).
// A = X fp32 [M,256] (inline cvt at STS); B = wcat half [320,256] k-major.
//   cols <256: resh = leaky(acc + b_res)  (half);  cols>=256: a0h (half)
// ---------------------------------------------------------------------------
__global__ __launch_bounds__(256, 2)
void hgemm_cat(const float* __restrict__ A, const __half* __restrict__ Bt,
               const float* __restrict__ bias0, const float* __restrict__ bias1,
               __half* __restrict__ resh, __half* __restrict__ a0h, int M)
{
    constexpr int KD    = 256;
    constexpr int BK    = 64;
    constexpr int NST   = KD / BK;           // 4
    constexpr int CTAM  = 64;
    constexpr int CTAN  = 160;
    constexpr int ABY   = CTAM * 128;        // 8 KB
    constexpr int BBY   = CTAN * 128;        // 20 KB
    constexpr int STAGE = ABY + BBY;
    constexpr int NT16  = CTAN / 32;         // 5
    constexpr int NT8   = 2 * NT16;          // 10

    extern __shared__ char smem[];
    const uint32_t sbase = (uint32_t)__cvta_generic_to_shared(smem);

    const int tid  = threadIdx.x;
    const int wid  = tid >> 5;
    const int lane = tid & 31;
    const int g = lane >> 2;
    const int l = lane & 3;
    const int quad = lane >> 3;
    const int lrow = lane & 7;
    const int warp_m = (wid & 3) * 16;
    const int warp_n = (wid >> 2) * (CTAN / 2);
    const int rowbase = blockIdx.x * CTAM;
    const int colbase = blockIdx.y * CTAN;

    const int pa_r = tid >> 3, pa_c = tid & 7;

    const int arow  = warp_m + (quad & 1) * 8 + lrow;
    const int ac_hi = quad >> 1;
    const int brow0 = warp_n + ((quad >> 1) & 1) * 8 + lrow;
    const int bc_lo = quad & 1;

    float c[NT8][4];
    #pragma unroll
    for (int ni = 0; ni < NT8; ni++)
        #pragma unroll
        for (int j = 0; j < 4; j++)
            c[ni][j] = 0.0f;

    float4 aR[2][2];

    auto ldgA = [&](int t) {
        const int kk = t * BK;
        #pragma unroll
        for (int i = 0; i < 2; i++) {
            int hc = tid + i * 256;          // half-chunk 0..511
            int r = hc >> 3, c8 = hc & 7;
            int grow = rowbase + r;
            if (grow < M) {
                const float4* src = reinterpret_cast<const float4*>(
                    A + (size_t)grow * KD + kk + c8 * 8);
                aR[i][0] = src[0];
                aR[i][1] = src[1];
            } else {
                aR[i][0] = make_float4(0.f, 0.f, 0.f, 0.f);
                aR[i][1] = make_float4(0.f, 0.f, 0.f, 0.f);
            }
        }
    };

    auto storeA = [&](int t) {
        char* st = smem + (t & 1) * STAGE;
        #pragma unroll
        for (int i = 0; i < 2; i++) {
            int hc = tid + i * 256;
            int r = hc >> 3, c8 = hc & 7;
            __half2 h0 = __float22half2_rn(make_float2(aR[i][0].x, aR[i][0].y));
            __half2 h1 = __float22half2_rn(make_float2(aR[i][0].z, aR[i][0].w));
            __half2 h2 = __float22half2_rn(make_float2(aR[i][1].x, aR[i][1].y));
            __half2 h3 = __float22half2_rn(make_float2(aR[i][1].z, aR[i][1].w));
            uint4 v;
            v.x = *reinterpret_cast<uint32_t*>(&h0);
            v.y = *reinterpret_cast<uint32_t*>(&h1);
            v.z = *reinterpret_cast<uint32_t*>(&h2);
            v.w = *reinterpret_cast<uint32_t*>(&h3);
            *reinterpret_cast<uint4*>(
                st + r * 128 + ((c8 ^ (r & 7)) << 4)) = v;
        }
    };

    auto issueB = [&](int t) {
        const int kk = t * BK;
        const uint32_t st = sbase + (t & 1) * STAGE;
        #pragma unroll
        for (int i = 0; i < 5; i++) {        // 160 rows x 8 chunks / 256 thr
            int r = pa_r + i * 32;
            const __half* src =
                Bt + (size_t)(colbase + r) * KD + kk + pa_c * 8;
            uint32_t dst = st + ABY + r * 128 + ((pa_c ^ (r & 7)) << 4);
            cp_async16(dst, src, 16u);
        }
        CP_COMMIT();
    };

    ldgA(0);
    issueB(0);
    issueB(1);
    storeA(0);
    CP_WAIT(1);
    __syncthreads();

    for (int t = 0; t < NST; t++) {
        const uint32_t st = sbase + (t & 1) * STAGE;
        if (t + 1 < NST) ldgA(t + 1);

        #pragma unroll
        for (int ks8 = 0; ks8 < BK / 8; ks8 += 2) {
            uint32_t af[4];
            {
                int cch = ks8 + ac_hi;
                uint32_t addr = st + arow * 128 + ((cch ^ (arow & 7)) << 4);
                LDSM_X4(af[0], af[1], af[2], af[3], addr);
            }
            #pragma unroll
            for (int nt = 0; nt < NT16; nt++) {
                uint32_t bf[4];
                int r = brow0 + nt * 16;
                int cch = ks8 + bc_lo;
                uint32_t addr = st + ABY + r * 128 + ((cch ^ (r & 7)) << 4);
                LDSM_X4(bf[0], bf[1], bf[2], bf[3], addr);
                MMA_F16(c[nt * 2 + 0], af, bf[0], bf[1]);
                MMA_F16(c[nt * 2 + 1], af, bf[2], bf[3]);
            }
        }
        __syncthreads();
        if (t + 1 < NST) {
            storeA(t + 1);
            if (t + 2 < NST) { issueB(t + 2); CP_WAIT(1); }
            else             { CP_WAIT(0); }
            __syncthreads();
        }
    }

    // ---- epilogue: bias + leaky, half outputs, per-tile column routing ----
    #pragma unroll
    for (int ni = 0; ni < NT8; ni++) {
        const int col = colbase + warp_n + ni * 8 + 2 * l;
        const bool isInit = (col >= 256);
        const float b0 = isInit ? bias1[col - 256] : bias0[col];
        const float b1 = isInit ? bias1[col - 255] : bias0[col + 1];
        #pragma unroll
        for (int hm = 0; hm < 2; hm++) {
            const int r = rowbase + warp_m + g + hm * 8;
            if (r >= M) continue;
            float ox = leaky(c[ni][hm * 2 + 0] + b0);
            float oy = leaky(c[ni][hm * 2 + 1] + b1);
            __half2 h = __float22half2_rn(make_float2(ox, oy));
            if (isInit)
                *reinterpret_cast<uint32_t*>(
                    a0h + (size_t)r * 64 + col - 256) =
                    *reinterpret_cast<uint32_t*>(&h);
            else
                *reinterpret_cast<uint32_t*>(
                    resh + (size_t)r * 256 + col) =
                    *reinterpret_cast<uint32_t*>(&h);
        }
    }
}

// ---------------------------------------------------------------------------
// FINAL GEMM: out = leaky(a2h @ wfT^T + b_fin) + resh.  128x128, fp32 out.
// ---------------------------------------------------------------------------
__global__ __launch_bounds__(256, 2)
void hgemm_fin(const __half* __restrict__ A, const __half* __restrict__ Bt,
               const float* __restrict__ bias, const __half* __restrict__ resh,
               float* __restrict__ C, int M)
{
    constexpr int KD    = 256;
    constexpr int BK    = 64;
    constexpr int NST   = KD / BK;
    constexpr int CTAN  = 128;
    constexpr int ABY   = 128 * 128;
    constexpr int BBY   = CTAN * 128;
    constexpr int STAGE = ABY + BBY;
    constexpr int NT16  = CTAN / 32;         // 4
    constexpr int NT8   = 2 * NT16;          // 8

    extern __shared__ char smem[];
    const uint32_t sbase = (uint32_t)__cvta_generic_to_shared(smem);

    const int tid  = threadIdx.x;
    const int wid  = tid >> 5;
    const int lane = tid & 31;
    const int g = lane >> 2;
    const int l = lane & 3;
    const int quad = lane >> 3;
    const int lrow = lane & 7;
    const int warp_m = (wid & 3) * 32;
    const int warp_n = (wid >> 2) * (CTAN / 2);
    const int rowbase = blockIdx.x * 128;
    const int colbase = blockIdx.y * CTAN;

    const int pa_r = tid >> 3, pa_c = tid & 7;
    const int arow  = warp_m + (quad & 1) * 8 + lrow;
    const int ac_hi = quad >> 1;
    const int brow0 = warp_n + ((quad >> 1) & 1) * 8 + lrow;
    const int bc_lo = quad & 1;

    float c[2][NT8][4];
    #pragma unroll
    for (int mi = 0; mi < 2; mi++)
        #pragma unroll
        for (int ni = 0; ni < NT8; ni++)
            #pragma unroll
            for (int j = 0; j < 4; j++)
                c[mi][ni][j] = 0.0f;

    auto issue = [&](int t) {
        const int kk = t * BK;
        const uint32_t st = sbase + (t & 1) * STAGE;
        #pragma unroll
        for (int i = 0; i < 4; i++) {
            int r = pa_r + i * 32;
            int grow = rowbase + r;
            bool v = grow < M;
            const __half* src =
                A + (size_t)(v ? grow : 0) * KD + kk + pa_c * 8;
            uint32_t dst = st + r * 128 + ((pa_c ^ (r & 7)) << 4);
            cp_async16(dst, src, v ? 16u : 0u);
        }
        #pragma unroll
        for (int i = 0; i < 4; i++) {
            int r = pa_r + i * 32;
            const __half* src =
                Bt + (size_t)(colbase + r) * KD + kk + pa_c * 8;
            uint32_t dst = st + ABY + r * 128 + ((pa_c ^ (r & 7)) << 4);
            cp_async16(dst, src, 16u);
        }
        CP_COMMIT();
    };

    issue(0);
    issue(1);
    CP_WAIT(1);
    __syncthreads();

    for (int t = 0; t < NST; t++) {
        const uint32_t st = sbase + (t & 1) * STAGE;
        #pragma unroll
        for (int ks8 = 0; ks8 < BK / 8; ks8 += 2) {
            uint32_t af[2][4];
            #pragma unroll
            for (int mi = 0; mi < 2; mi++) {
                int r = arow + mi * 16;
                int cch = ks8 + ac_hi;
                uint32_t addr = st + r * 128 + ((cch ^ (r & 7)) << 4);
                LDSM_X4(af[mi][0], af[mi][1], af[mi][2], af[mi][3], addr);
            }
            #pragma unroll
            for (int nt = 0; nt < NT16; nt++) {
                uint32_t bf[4];
                int r = brow0 + nt * 16;
                int cch = ks8 + bc_lo;
                uint32_t addr = st + ABY + r * 128 + ((cch ^ (r & 7)) << 4);
                LDSM_X4(bf[0], bf[1], bf[2], bf[3], addr);
                MMA_F16(c[0][nt * 2 + 0], af[0], bf[0], bf[1]);
                MMA_F16(c[1][nt * 2 + 0], af[1], bf[0], bf[1]);
                MMA_F16(c[0][nt * 2 + 1], af[0], bf[2], bf[3]);
                MMA_F16(c[1][nt * 2 + 1], af[1], bf[2], bf[3]);
            }
        }
        __syncthreads();
        if (t + 1 < NST) {
            if (t + 2 < NST) { issue(t + 2); CP_WAIT(1); }
            else             { CP_WAIT(0); }
            __syncthreads();
        }
    }

    #pragma unroll
    for (int mi = 0; mi < 2; mi++) {
        #pragma unroll
        for (int ni = 0; ni < NT8; ni++) {
            const int col = colbase + warp_n + ni * 8 + 2 * l;
            const float b0 = bias[col];
            const float b1 = bias[col + 1];
            #pragma unroll
            for (int hm = 0; hm < 2; hm++) {
                const int r = rowbase + warp_m + mi * 16 + g + hm * 8;
                if (r >= M) continue;
                uint32_t ru = *reinterpret_cast<const uint32_t*>(
                    resh + (size_t)r * 256 + col);
                float2 rv = __half22float2(*reinterpret_cast<__half2*>(&ru));
                float2 o;
                o.x = leaky(c[mi][ni][hm * 2 + 0] + b0) + rv.x;
                o.y = leaky(c[mi][ni][hm * 2 + 1] + b1) + rv.y;
                *reinterpret_cast<float2*>(C + (size_t)r * 256 + col) = o;
            }
        }
    }
}

// ---------------------------------------------------------------------------
// gather1: a1h[p, 64:128] = mean_k a0h[idx[p,k], 0:64]
// 2 points per warp, 16 lanes/point, uint2 (8B) loads. 16 pts/CTA.
// ---------------------------------------------------------------------------
__global__ __launch_bounds__(256)
void gather1(const __half* __restrict__ a0h, const int* __restrict__ idx,
             __half* __restrict__ a1h, int N)
{
    __shared__ int is[16][16];
    const int tid  = threadIdx.x;
    const int wid  = tid >> 5;
    const int lane = tid & 31;
    const int pbase = blockIdx.x * 16;

    {
        int pp = pbase + (tid >> 4);
        is[tid >> 4][tid & 15] =
            (pp < N) ? idx[(size_t)pp * 16 + (tid & 15)] : 0;
    }
    __syncthreads();

    const int pl = wid * 2 + (lane >> 4);   // local point 0..15
    const int sl = lane & 15;
    const int p  = pbase + pl;
    if (p >= N) return;

    const uint2* src = reinterpret_cast<const uint2*>(a0h);  // 16 uint2/row
    float s0 = 0.f, s1 = 0.f, s2 = 0.f, s3 = 0.f;
    #pragma unroll
    for (int k = 0; k < 16; k++) {
        uint2 u = src[(size_t)is[pl][k] * 16 + sl];
        float2 f0 = __half22float2(*reinterpret_cast<__half2*>(&u.x));
        float2 f1 = __half22float2(*reinterpret_cast<__half2*>(&u.y));
        s0 += f0.x; s1 += f0.y; s2 += f1.x; s3 += f1.y;
    }
    __half2 o0 = __float22half2_rn(make_float2(s0 * 0.0625f, s1 * 0.0625f));
    __half2 o1 = __float22half2_rn(make_float2(s2 * 0.0625f, s3 * 0.0625f));
    uint2 o;
    o.x = *reinterpret_cast<uint32_t*>(&o0);
    o.y = *reinterpret_cast<uint32_t*>(&o1);
    *reinterpret_cast<uint2*>(a1h + (size_t)p * 128 + 64 + sl * 4) = o;
}

// ---------------------------------------------------------------------------
// gather2: a2h[p, 128:256] = mean_k a1h[idx[p,k], 0:128]
// 2 points per warp, 16 lanes/point, uint4 (16B) loads. 16 pts/CTA.
// ---------------------------------------------------------------------------
__global__ __launch_bounds__(256)
void gather2(const __half* __restrict__ a1h, const int* __restrict__ idx,
             __half* __restrict__ a2h, int N)
{
    __shared__ int is[16][16];
    const int tid  = threadIdx.x;
    const int wid  = tid >> 5;
    const int lane = tid & 31;
    const int pbase = blockIdx.x * 16;

    {
        int pp = pbase + (tid >> 4);
        is[tid >> 4][tid & 15] =
            (pp < N) ? idx[(size_t)pp * 16 + (tid & 15)] : 0;
    }
    __syncthreads();

    const int pl = wid * 2 + (lane >> 4);
    const int sl = lane & 15;
    const int p  = pbase + pl;
    if (p >= N) return;

    const uint4* src = reinterpret_cast<const uint4*>(a1h);  // 16 uint4/row
    float s[8];
    #pragma unroll
    for (int i = 0; i < 8; i++) s[i] = 0.f;
    #pragma unroll
    for (int k = 0; k < 16; k++) {
        uint4 u = src[(size_t)is[pl][k] * 16 + sl];
        float2 f0 = __half22float2(*reinterpret_cast<__half2*>(&u.x));
        float2 f1 = __half22float2(*reinterpret_cast<__half2*>(&u.y));
        float2 f2 = __half22float2(*reinterpret_cast<__half2*>(&u.z));
        float2 f3 = __half22float2(*reinterpret_cast<__half2*>(&u.w));
        s[0] += f0.x; s[1] += f0.y; s[2] += f1.x; s[3] += f1.y;
        s[4] += f2.x; s[5] += f2.y; s[6] += f3.x; s[7] += f3.y;
    }
    __half2 o0 = __float22half2_rn(make_float2(s[0] * 0.0625f, s[1] * 0.0625f));
    __half2 o1 = __float22half2_rn(make_float2(s[2] * 0.0625f, s[3] * 0.0625f));
    __half2 o2 = __float22half2_rn(make_float2(s[4] * 0.0625f, s[5] * 0.0625f));
    __half2 o3 = __float22half2_rn(make_float2(s[6] * 0.0625f, s[7] * 0.0625f));
    uint4 o;
    o.x = *reinterpret_cast<uint32_t*>(&o0);
    o.y = *reinterpret_cast<uint32_t*>(&o1);
    o.z = *reinterpret_cast<uint32_t*>(&o2);
    o.w = *reinterpret_cast<uint32_t*>(&o3);
    *reinterpret_cast<uint4*>(a2h + (size_t)p * 256 + 128 + sl * 8) = o;
}

// ---------------------------------------------------------------------------
extern "C" void kernel_launch(void* const* d_in, const int* in_sizes, int n_in,
                              void* d_out, int out_size)
{
    const float* X      = (const float*)d_in[0];
    const float* geom   = (const float*)d_in[1];
    const int*   idx    = (const int*)  d_in[2];
    const float* w_res  = (const float*)d_in[3];
    const float* b_res  = (const float*)d_in[4];
    const float* w_init = (const float*)d_in[5];
    const float* b_init = (const float*)d_in[6];
    const float* w_g1   = (const float*)d_in[7];
    const float* b_g1   = (const float*)d_in[8];
    const float* w_g2   = (const float*)d_in[9];
    const float* b_g2   = (const float*)d_in[10];
    const float* w_fin  = (const float*)d_in[11];
    const float* b_fin  = (const float*)d_in[12];
    float* out = (float*)d_out;

    const int N = in_sizes[0] / DIM;

    __half *resh, *a0h, *a1h, *a2h, *wcat, *wfT;
    cudaGetSymbolAddress((void**)&resh, g_resh);
    cudaGetSymbolAddress((void**)&a0h,  g_a0h);
    cudaGetSymbolAddress((void**)&a1h,  g_a1h);
    cudaGetSymbolAddress((void**)&a2h,  g_a2h);
    cudaGetSymbolAddress((void**)&wcat, g_wcat);
    cudaGetSymbolAddress((void**)&wfT,  g_wfT);

    constexpr int SMEM_CAT   = 2 * (64 * 128 + 160 * 128);   // 56 KB
    constexpr int SMEM_FINAL = 2 * (128 * 128 + 128 * 128);  // 64 KB
    cudaFuncSetAttribute(hgemm_cat,
                         cudaFuncAttributeMaxDynamicSharedMemorySize, SMEM_CAT);
    cudaFuncSetAttribute(hgemm_fin,
                         cudaFuncAttributeMaxDynamicSharedMemorySize, SMEM_FINAL);

    const int gridP  = (N + 7) / 8;
    const int gridG  = (N + 15) / 16;

    // 0) weight prep + geometry MLP (one launch)
    prep_geom<<<144 + gridP, 256>>>(w_res, w_init, w_fin, wcat, wfT,
                                    geom, w_g1, b_g1, w_g2, b_g2,
                                    a1h, a2h, N);
    // 1+2) fused: resh (half) + a0h (half) = leaky(X @ [w_res|w_init] + b)
    hgemm_cat<<<dim3((N + 63) / 64, 2), 256, SMEM_CAT>>>(
        X, wcat, b_res, b_init, resh, a0h, N);
    // 3) gather half of LFA1
    gather1<<<gridG, 256>>>(a0h, idx, a1h, N);
    // 4) gather half of LFA2
    gather2<<<gridG, 256>>>(a1h, idx, a2h, N);
    // 5) out = leaky(a2 @ w_fin + b_fin) + resh
    hgemm_fin<<<dim3((N + 127) / 128, 2), 256, SMEM_FINAL>>>(
        a2h, wfT, b_fin, resh, out, N);
}

// round 10
// speedup vs baseline: 3.7588x; 1.0252x over previous
#include <cuda_runtime.h>
#include <cuda_fp16.h>
#include <cstdint>

#define NPTS 50000
#define DIM 256

// ---------------- scratch (no-alloc rule: __device__ globals) --------------
__device__ __half g_resh[NPTS * DIM];       // residual, half
__device__ __half g_a0h[NPTS * (DIM / 4)];  // init MLP out, half
__device__ __half g_a1h[NPTS * (DIM / 2)];  // LFA1 out, half
__device__ __half g_a2h[NPTS * DIM];        // LFA2 out, half
__device__ __half g_wcat[(DIM + DIM / 4) * DIM]; // [w_res^T ; w_init^T] [320,256]
__device__ __half g_wfT[DIM * DIM];         // w_fin^T half [256,256]

__device__ __forceinline__ float leaky(float x) {
    return x >= 0.0f ? x : 0.2f * x;
}

#define MMA_F16(c, a, b0, b1)                                             \
    asm volatile(                                                         \
        "mma.sync.aligned.m16n8k16.row.col.f32.f16.f16.f32 "              \
        "{%0,%1,%2,%3}, {%4,%5,%6,%7}, {%8,%9}, {%0,%1,%2,%3};"           \
        : "+f"((c)[0]), "+f"((c)[1]), "+f"((c)[2]), "+f"((c)[3])          \
        : "r"((a)[0]), "r"((a)[1]), "r"((a)[2]), "r"((a)[3]),             \
          "r"(b0), "r"(b1))

#define LDSM_X4(r0, r1, r2, r3, addr)                                     \
    asm volatile(                                                         \
        "ldmatrix.sync.aligned.m8n8.x4.shared.b16 {%0,%1,%2,%3}, [%4];"   \
        : "=r"(r0), "=r"(r1), "=r"(r2), "=r"(r3) : "r"(addr))

__device__ __forceinline__ void cp_async16(uint32_t dst, const void* src,
                                           uint32_t src_bytes) {
    asm volatile("cp.async.ca.shared.global [%0], [%1], 16, %2;"
                 :: "r"(dst), "l"(src), "r"(src_bytes));
}
#define CP_COMMIT() asm volatile("cp.async.commit_group;")
#define CP_WAIT(n)  asm volatile("cp.async.wait_group %0;" :: "n"(n))

__device__ __forceinline__ __half2 u2h2(uint32_t u) {
    return *reinterpret_cast<__half2*>(&u);
}

// ---------------------------------------------------------------------------
// prep_geom: blocks [0,144) weight prep; blocks [144,...) geometry MLP.
// ---------------------------------------------------------------------------
__global__ __launch_bounds__(256)
void prep_geom(const float* __restrict__ w_res,
               const float* __restrict__ w_init,
               const float* __restrict__ w_fin,
               __half* __restrict__ wcat, __half* __restrict__ wfT,
               const float* __restrict__ geom,
               const float* __restrict__ wg1, const float* __restrict__ bg1,
               const float* __restrict__ wg2, const float* __restrict__ bg2,
               __half* __restrict__ a1h, __half* __restrict__ a2h, int N)
{
    const int tid = threadIdx.x;

    if (blockIdx.x < 144) {
        __shared__ float t[32][33];
        const float* in;
        __half* out;
        int K = 256, Nc, bx;
        if (blockIdx.x < 64)      { in = w_res;  out = wcat; Nc = 256; bx = blockIdx.x; }
        else if (blockIdx.x < 80) { in = w_init; out = wcat + 256 * 256; Nc = 64;
                                    bx = blockIdx.x - 64; }
        else                      { in = w_fin;  out = wfT;  Nc = 256; bx = blockIdx.x - 80; }
        int tx = tid & 31, ty = tid >> 5;
        int nTx = Nc / 32;
        int n0 = (bx % nTx) * 32;
        int k0 = (bx / nTx) * 32;
        for (int i = ty; i < 32; i += 8)
            t[i][tx] = in[(size_t)(k0 + i) * Nc + n0 + tx];
        __syncthreads();
        for (int i = ty; i < 32; i += 8)
            out[(size_t)(n0 + i) * K + k0 + tx] = __float2half(t[tx][i]);
        return;
    }

    __shared__ uint2 gsm[8][16];
    const int wid  = tid >> 5;
    const int lane = tid & 31;
    const int pbase = (blockIdx.x - 144) * 8;

    if (tid < 128) {
        int pp = pbase + (tid >> 4);
        int k  = tid & 15;
        float4 gv = (pp < N)
            ? reinterpret_cast<const float4*>(geom)[(size_t)pp * 16 + k]
            : make_float4(0.f, 0.f, 0.f, 0.f);
        __half2 g01 = __float22half2_rn(make_float2(gv.x, gv.y));
        __half2 g23 = __float22half2_rn(make_float2(gv.z, gv.w));
        uint2 u;
        u.x = *reinterpret_cast<uint32_t*>(&g01);
        u.y = *reinterpret_cast<uint32_t*>(&g23);
        gsm[tid >> 4][k] = u;
    }
    __syncthreads();

    const int p = pbase + wid;
    if (p >= N) return;

    const int ch0 = lane * 6;
    __half2 w0[3], w1[3], w2[3], w3[3], bb[3];
    #pragma unroll
    for (int j = 0; j < 3; j++) {
        int ch = ch0 + 2 * j;
        const float* wsrc;
        const float* bsrc;
        int str, cb;
        if (ch < 64) { wsrc = wg1; bsrc = bg1; str = 64;  cb = ch; }
        else         { wsrc = wg2; bsrc = bg2; str = 128; cb = ch - 64; }
        w0[j] = __floats2half2_rn(wsrc[0 * str + cb], wsrc[0 * str + cb + 1]);
        w1[j] = __floats2half2_rn(wsrc[1 * str + cb], wsrc[1 * str + cb + 1]);
        w2[j] = __floats2half2_rn(wsrc[2 * str + cb], wsrc[2 * str + cb + 1]);
        w3[j] = __floats2half2_rn(wsrc[3 * str + cb], wsrc[3 * str + cb + 1]);
        bb[j] = __floats2half2_rn(bsrc[cb], bsrc[cb + 1]);
    }

    const __half2 zero = __float2half2_rn(0.0f);
    const __half2 p02  = __float2half2_rn(0.2f);
    float acc[6];
    #pragma unroll
    for (int i = 0; i < 6; i++) acc[i] = 0.0f;

    #pragma unroll
    for (int k = 0; k < 16; k++) {
        uint2 u = gsm[wid][k];
        __half2 g01 = u2h2(u.x);
        __half2 g23 = u2h2(u.y);
        __half2 gb0 = __low2half2(g01);
        __half2 gb1 = __high2half2(g01);
        __half2 gb2 = __low2half2(g23);
        __half2 gb3 = __high2half2(g23);
        #pragma unroll
        for (int j = 0; j < 3; j++) {
            __half2 v = bb[j];
            v = __hfma2(gb0, w0[j], v);
            v = __hfma2(gb1, w1[j], v);
            v = __hfma2(gb2, w2[j], v);
            v = __hfma2(gb3, w3[j], v);
            __half2 lk = __hfma2(__hmin2(v, zero), p02, __hmax2(v, zero));
            float2 f = __half22float2(lk);
            acc[2 * j]     += f.x;
            acc[2 * j + 1] += f.y;
        }
    }

    #pragma unroll
    for (int j = 0; j < 3; j++) {
        int ch = ch0 + 2 * j;
        __half2 o = __float22half2_rn(
            make_float2(acc[2 * j] * 0.0625f, acc[2 * j + 1] * 0.0625f));
        if (ch < 64)
            *reinterpret_cast<uint32_t*>(a1h + (size_t)p * 128 + ch) =
                *reinterpret_cast<uint32_t*>(&o);
        else
            *reinterpret_cast<uint32_t*>(a2h + (size_t)p * 256 + (ch - 64)) =
                *reinterpret_cast<uint32_t*>(&o);
    }
}

// ---------------------------------------------------------------------------
// CAT GEMM (fused stage 1+2): CTA tile 64 x 320, grid.y = 1 — single X pass.
// A = X fp32 [M,256] (inline cvt at STS); B = wcat half [320,256] k-major.
// ---------------------------------------------------------------------------
__global__ __launch_bounds__(256, 2)
void hgemm_cat(const float* __restrict__ A, const __half* __restrict__ Bt,
               const float* __restrict__ bias0, const float* __restrict__ bias1,
               __half* __restrict__ resh, __half* __restrict__ a0h, int M)
{
    constexpr int KD    = 256;
    constexpr int BK    = 64;
    constexpr int NST   = KD / BK;           // 4
    constexpr int CTAM  = 64;
    constexpr int CTAN  = 320;
    constexpr int ABY   = CTAM * 128;        // 8 KB
    constexpr int BBY   = CTAN * 128;        // 40 KB
    constexpr int STAGE = ABY + BBY;         // 48 KB
    constexpr int NT16  = CTAN / 32;         // 10
    constexpr int NT8   = 2 * NT16;          // 20

    extern __shared__ char smem[];
    const uint32_t sbase = (uint32_t)__cvta_generic_to_shared(smem);

    const int tid  = threadIdx.x;
    const int wid  = tid >> 5;
    const int lane = tid & 31;
    const int g = lane >> 2;
    const int l = lane & 3;
    const int quad = lane >> 3;
    const int lrow = lane & 7;
    const int warp_m = (wid & 3) * 16;
    const int warp_n = (wid >> 2) * (CTAN / 2);
    const int rowbase = blockIdx.x * CTAM;

    const int pa_r = tid >> 3, pa_c = tid & 7;

    const int arow  = warp_m + (quad & 1) * 8 + lrow;
    const int ac_hi = quad >> 1;
    const int brow0 = warp_n + ((quad >> 1) & 1) * 8 + lrow;
    const int bc_lo = quad & 1;

    float c[NT8][4];
    #pragma unroll
    for (int ni = 0; ni < NT8; ni++)
        #pragma unroll
        for (int j = 0; j < 4; j++)
            c[ni][j] = 0.0f;

    float4 aR[2][2];

    auto ldgA = [&](int t) {
        const int kk = t * BK;
        #pragma unroll
        for (int i = 0; i < 2; i++) {
            int hc = tid + i * 256;
            int r = hc >> 3, c8 = hc & 7;
            int grow = rowbase + r;
            if (grow < M) {
                const float4* src = reinterpret_cast<const float4*>(
                    A + (size_t)grow * KD + kk + c8 * 8);
                aR[i][0] = src[0];
                aR[i][1] = src[1];
            } else {
                aR[i][0] = make_float4(0.f, 0.f, 0.f, 0.f);
                aR[i][1] = make_float4(0.f, 0.f, 0.f, 0.f);
            }
        }
    };

    auto storeA = [&](int t) {
        char* st = smem + (t & 1) * STAGE;
        #pragma unroll
        for (int i = 0; i < 2; i++) {
            int hc = tid + i * 256;
            int r = hc >> 3, c8 = hc & 7;
            __half2 h0 = __float22half2_rn(make_float2(aR[i][0].x, aR[i][0].y));
            __half2 h1 = __float22half2_rn(make_float2(aR[i][0].z, aR[i][0].w));
            __half2 h2 = __float22half2_rn(make_float2(aR[i][1].x, aR[i][1].y));
            __half2 h3 = __float22half2_rn(make_float2(aR[i][1].z, aR[i][1].w));
            uint4 v;
            v.x = *reinterpret_cast<uint32_t*>(&h0);
            v.y = *reinterpret_cast<uint32_t*>(&h1);
            v.z = *reinterpret_cast<uint32_t*>(&h2);
            v.w = *reinterpret_cast<uint32_t*>(&h3);
            *reinterpret_cast<uint4*>(
                st + r * 128 + ((c8 ^ (r & 7)) << 4)) = v;
        }
    };

    auto issueB = [&](int t) {
        const int kk = t * BK;
        const uint32_t st = sbase + (t & 1) * STAGE;
        #pragma unroll
        for (int i = 0; i < 10; i++) {       // 320 rows x 8 chunks / 256 thr
            int r = pa_r + i * 32;
            const __half* src =
                Bt + (size_t)r * KD + kk + pa_c * 8;
            uint32_t dst = st + ABY + r * 128 + ((pa_c ^ (r & 7)) << 4);
            cp_async16(dst, src, 16u);
        }
        CP_COMMIT();
    };

    ldgA(0);
    issueB(0);
    issueB(1);
    storeA(0);
    CP_WAIT(1);
    __syncthreads();

    for (int t = 0; t < NST; t++) {
        const uint32_t st = sbase + (t & 1) * STAGE;
        if (t + 1 < NST) ldgA(t + 1);

        #pragma unroll
        for (int ks8 = 0; ks8 < BK / 8; ks8 += 2) {
            uint32_t af[4];
            {
                int cch = ks8 + ac_hi;
                uint32_t addr = st + arow * 128 + ((cch ^ (arow & 7)) << 4);
                LDSM_X4(af[0], af[1], af[2], af[3], addr);
            }
            #pragma unroll
            for (int nt = 0; nt < NT16; nt++) {
                uint32_t bf[4];
                int r = brow0 + nt * 16;
                int cch = ks8 + bc_lo;
                uint32_t addr = st + ABY + r * 128 + ((cch ^ (r & 7)) << 4);
                LDSM_X4(bf[0], bf[1], bf[2], bf[3], addr);
                MMA_F16(c[nt * 2 + 0], af, bf[0], bf[1]);
                MMA_F16(c[nt * 2 + 1], af, bf[2], bf[3]);
            }
        }
        __syncthreads();
        if (t + 1 < NST) {
            storeA(t + 1);
            if (t + 2 < NST) { issueB(t + 2); CP_WAIT(1); }
            else             { CP_WAIT(0); }
            __syncthreads();
        }
    }

    // ---- epilogue: bias + leaky, half outputs, per-tile column routing ----
    #pragma unroll
    for (int ni = 0; ni < NT8; ni++) {
        const int col = warp_n + ni * 8 + 2 * l;
        const bool isInit = (col >= 256);
        const float b0 = isInit ? bias1[col - 256] : bias0[col];
        const float b1 = isInit ? bias1[col - 255] : bias0[col + 1];
        #pragma unroll
        for (int hm = 0; hm < 2; hm++) {
            const int r = rowbase + warp_m + g + hm * 8;
            if (r >= M) continue;
            float ox = leaky(c[ni][hm * 2 + 0] + b0);
            float oy = leaky(c[ni][hm * 2 + 1] + b1);
            __half2 h = __float22half2_rn(make_float2(ox, oy));
            if (isInit)
                *reinterpret_cast<uint32_t*>(
                    a0h + (size_t)r * 64 + col - 256) =
                    *reinterpret_cast<uint32_t*>(&h);
            else
                *reinterpret_cast<uint32_t*>(
                    resh + (size_t)r * 256 + col) =
                    *reinterpret_cast<uint32_t*>(&h);
        }
    }
}

// ---------------------------------------------------------------------------
// FINAL GEMM: out = leaky(a2h @ wfT^T + b_fin) + resh.  128x128, fp32 out.
// ---------------------------------------------------------------------------
__global__ __launch_bounds__(256, 2)
void hgemm_fin(const __half* __restrict__ A, const __half* __restrict__ Bt,
               const float* __restrict__ bias, const __half* __restrict__ resh,
               float* __restrict__ C, int M)
{
    constexpr int KD    = 256;
    constexpr int BK    = 64;
    constexpr int NST   = KD / BK;
    constexpr int CTAN  = 128;
    constexpr int ABY   = 128 * 128;
    constexpr int BBY   = CTAN * 128;
    constexpr int STAGE = ABY + BBY;
    constexpr int NT16  = CTAN / 32;         // 4
    constexpr int NT8   = 2 * NT16;          // 8

    extern __shared__ char smem[];
    const uint32_t sbase = (uint32_t)__cvta_generic_to_shared(smem);

    const int tid  = threadIdx.x;
    const int wid  = tid >> 5;
    const int lane = tid & 31;
    const int g = lane >> 2;
    const int l = lane & 3;
    const int quad = lane >> 3;
    const int lrow = lane & 7;
    const int warp_m = (wid & 3) * 32;
    const int warp_n = (wid >> 2) * (CTAN / 2);
    const int rowbase = blockIdx.x * 128;
    const int colbase = blockIdx.y * CTAN;

    const int pa_r = tid >> 3, pa_c = tid & 7;
    const int arow  = warp_m + (quad & 1) * 8 + lrow;
    const int ac_hi = quad >> 1;
    const int brow0 = warp_n + ((quad >> 1) & 1) * 8 + lrow;
    const int bc_lo = quad & 1;

    float c[2][NT8][4];
    #pragma unroll
    for (int mi = 0; mi < 2; mi++)
        #pragma unroll
        for (int ni = 0; ni < NT8; ni++)
            #pragma unroll
            for (int j = 0; j < 4; j++)
                c[mi][ni][j] = 0.0f;

    auto issue = [&](int t) {
        const int kk = t * BK;
        const uint32_t st = sbase + (t & 1) * STAGE;
        #pragma unroll
        for (int i = 0; i < 4; i++) {
            int r = pa_r + i * 32;
            int grow = rowbase + r;
            bool v = grow < M;
            const __half* src =
                A + (size_t)(v ? grow : 0) * KD + kk + pa_c * 8;
            uint32_t dst = st + r * 128 + ((pa_c ^ (r & 7)) << 4);
            cp_async16(dst, src, v ? 16u : 0u);
        }
        #pragma unroll
        for (int i = 0; i < 4; i++) {
            int r = pa_r + i * 32;
            const __half* src =
                Bt + (size_t)(colbase + r) * KD + kk + pa_c * 8;
            uint32_t dst = st + ABY + r * 128 + ((pa_c ^ (r & 7)) << 4);
            cp_async16(dst, src, 16u);
        }
        CP_COMMIT();
    };

    issue(0);
    issue(1);
    CP_WAIT(1);
    __syncthreads();

    for (int t = 0; t < NST; t++) {
        const uint32_t st = sbase + (t & 1) * STAGE;
        #pragma unroll
        for (int ks8 = 0; ks8 < BK / 8; ks8 += 2) {
            uint32_t af[2][4];
            #pragma unroll
            for (int mi = 0; mi < 2; mi++) {
                int r = arow + mi * 16;
                int cch = ks8 + ac_hi;
                uint32_t addr = st + r * 128 + ((cch ^ (r & 7)) << 4);
                LDSM_X4(af[mi][0], af[mi][1], af[mi][2], af[mi][3], addr);
            }
            #pragma unroll
            for (int nt = 0; nt < NT16; nt++) {
                uint32_t bf[4];
                int r = brow0 + nt * 16;
                int cch = ks8 + bc_lo;
                uint32_t addr = st + ABY + r * 128 + ((cch ^ (r & 7)) << 4);
                LDSM_X4(bf[0], bf[1], bf[2], bf[3], addr);
                MMA_F16(c[0][nt * 2 + 0], af[0], bf[0], bf[1]);
                MMA_F16(c[1][nt * 2 + 0], af[1], bf[0], bf[1]);
                MMA_F16(c[0][nt * 2 + 1], af[0], bf[2], bf[3]);
                MMA_F16(c[1][nt * 2 + 1], af[1], bf[2], bf[3]);
            }
        }
        __syncthreads();
        if (t + 1 < NST) {
            if (t + 2 < NST) { issue(t + 2); CP_WAIT(1); }
            else             { CP_WAIT(0); }
            __syncthreads();
        }
    }

    #pragma unroll
    for (int mi = 0; mi < 2; mi++) {
        #pragma unroll
        for (int ni = 0; ni < NT8; ni++) {
            const int col = colbase + warp_n + ni * 8 + 2 * l;
            const float b0 = bias[col];
            const float b1 = bias[col + 1];
            #pragma unroll
            for (int hm = 0; hm < 2; hm++) {
                const int r = rowbase + warp_m + mi * 16 + g + hm * 8;
                if (r >= M) continue;
                uint32_t ru = *reinterpret_cast<const uint32_t*>(
                    resh + (size_t)r * 256 + col);
                float2 rv = __half22float2(u2h2(ru));
                float2 o;
                o.x = leaky(c[mi][ni][hm * 2 + 0] + b0) + rv.x;
                o.y = leaky(c[mi][ni][hm * 2 + 1] + b1) + rv.y;
                *reinterpret_cast<float2*>(C + (size_t)r * 256 + col) = o;
            }
        }
    }
}

// ---------------------------------------------------------------------------
// gather1: a1h[p, 64:128] = mean_k a0h[idx[p,k], 0:64]
// 4 points per warp, 8 lanes/point, uint4 loads, pairwise HADD2 pre-reduce.
// ---------------------------------------------------------------------------
__global__ __launch_bounds__(256)
void gather1(const __half* __restrict__ a0h, const int* __restrict__ idx,
             __half* __restrict__ a1h, int N)
{
    __shared__ int is[32][16];
    const int tid  = threadIdx.x;
    const int wid  = tid >> 5;
    const int lane = tid & 31;
    const int pbase = blockIdx.x * 32;

    #pragma unroll
    for (int i = 0; i < 2; i++) {
        int e = tid + i * 256;
        int pp = pbase + (e >> 4);
        is[e >> 4][e & 15] = (pp < N) ? idx[(size_t)pp * 16 + (e & 15)] : 0;
    }
    __syncthreads();

    const int pl = wid * 4 + (lane >> 3);   // local point 0..31
    const int sl = lane & 7;
    const int p  = pbase + pl;
    if (p >= N) return;

    const uint4* src = reinterpret_cast<const uint4*>(a0h);  // 8 uint4/row
    float s[8];
    #pragma unroll
    for (int i = 0; i < 8; i++) s[i] = 0.f;

    #pragma unroll
    for (int k = 0; k < 16; k += 2) {
        uint4 ua = src[(size_t)is[pl][k]     * 8 + sl];
        uint4 ub = src[(size_t)is[pl][k + 1] * 8 + sl];
        __half2 h0 = __hadd2(u2h2(ua.x), u2h2(ub.x));
        __half2 h1 = __hadd2(u2h2(ua.y), u2h2(ub.y));
        __half2 h2 = __hadd2(u2h2(ua.z), u2h2(ub.z));
        __half2 h3 = __hadd2(u2h2(ua.w), u2h2(ub.w));
        float2 f0 = __half22float2(h0);
        float2 f1 = __half22float2(h1);
        float2 f2 = __half22float2(h2);
        float2 f3 = __half22float2(h3);
        s[0] += f0.x; s[1] += f0.y; s[2] += f1.x; s[3] += f1.y;
        s[4] += f2.x; s[5] += f2.y; s[6] += f3.x; s[7] += f3.y;
    }

    __half2 o0 = __float22half2_rn(make_float2(s[0] * 0.0625f, s[1] * 0.0625f));
    __half2 o1 = __float22half2_rn(make_float2(s[2] * 0.0625f, s[3] * 0.0625f));
    __half2 o2 = __float22half2_rn(make_float2(s[4] * 0.0625f, s[5] * 0.0625f));
    __half2 o3 = __float22half2_rn(make_float2(s[6] * 0.0625f, s[7] * 0.0625f));
    uint4 o;
    o.x = *reinterpret_cast<uint32_t*>(&o0);
    o.y = *reinterpret_cast<uint32_t*>(&o1);
    o.z = *reinterpret_cast<uint32_t*>(&o2);
    o.w = *reinterpret_cast<uint32_t*>(&o3);
    *reinterpret_cast<uint4*>(a1h + (size_t)p * 128 + 64 + sl * 8) = o;
}

// ---------------------------------------------------------------------------
// gather2: a2h[p, 128:256] = mean_k a1h[idx[p,k], 0:128]
// 2 points per warp, 16 lanes/point, uint4 loads, pairwise HADD2 pre-reduce.
// ---------------------------------------------------------------------------
__global__ __launch_bounds__(256)
void gather2(const __half* __restrict__ a1h, const int* __restrict__ idx,
             __half* __restrict__ a2h, int N)
{
    __shared__ int is[16][16];
    const int tid  = threadIdx.x;
    const int wid  = tid >> 5;
    const int lane = tid & 31;
    const int pbase = blockIdx.x * 16;

    {
        int pp = pbase + (tid >> 4);
        is[tid >> 4][tid & 15] =
            (pp < N) ? idx[(size_t)pp * 16 + (tid & 15)] : 0;
    }
    __syncthreads();

    const int pl = wid * 2 + (lane >> 4);
    const int sl = lane & 15;
    const int p  = pbase + pl;
    if (p >= N) return;

    const uint4* src = reinterpret_cast<const uint4*>(a1h);  // 16 uint4/row
    float s[8];
    #pragma unroll
    for (int i = 0; i < 8; i++) s[i] = 0.f;

    #pragma unroll
    for (int k = 0; k < 16; k += 2) {
        uint4 ua = src[(size_t)is[pl][k]     * 16 + sl];
        uint4 ub = src[(size_t)is[pl][k + 1] * 16 + sl];
        __half2 h0 = __hadd2(u2h2(ua.x), u2h2(ub.x));
        __half2 h1 = __hadd2(u2h2(ua.y), u2h2(ub.y));
        __half2 h2 = __hadd2(u2h2(ua.z), u2h2(ub.z));
        __half2 h3 = __hadd2(u2h2(ua.w), u2h2(ub.w));
        float2 f0 = __half22float2(h0);
        float2 f1 = __half22float2(h1);
        float2 f2 = __half22float2(h2);
        float2 f3 = __half22float2(h3);
        s[0] += f0.x; s[1] += f0.y; s[2] += f1.x; s[3] += f1.y;
        s[4] += f2.x; s[5] += f2.y; s[6] += f3.x; s[7] += f3.y;
    }

    __half2 o0 = __float22half2_rn(make_float2(s[0] * 0.0625f, s[1] * 0.0625f));
    __half2 o1 = __float22half2_rn(make_float2(s[2] * 0.0625f, s[3] * 0.0625f));
    __half2 o2 = __float22half2_rn(make_float2(s[4] * 0.0625f, s[5] * 0.0625f));
    __half2 o3 = __float22half2_rn(make_float2(s[6] * 0.0625f, s[7] * 0.0625f));
    uint4 o;
    o.x = *reinterpret_cast<uint32_t*>(&o0);
    o.y = *reinterpret_cast<uint32_t*>(&o1);
    o.z = *reinterpret_cast<uint32_t*>(&o2);
    o.w = *reinterpret_cast<uint32_t*>(&o3);
    *reinterpret_cast<uint4*>(a2h + (size_t)p * 256 + 128 + sl * 8) = o;
}

// ---------------------------------------------------------------------------
extern "C" void kernel_launch(void* const* d_in, const int* in_sizes, int n_in,
                              void* d_out, int out_size)
{
    const float* X      = (const float*)d_in[0];
    const float* geom   = (const float*)d_in[1];
    const int*   idx    = (const int*)  d_in[2];
    const float* w_res  = (const float*)d_in[3];
    const float* b_res  = (const float*)d_in[4];
    const float* w_init = (const float*)d_in[5];
    const float* b_init = (const float*)d_in[6];
    const float* w_g1   = (const float*)d_in[7];
    const float* b_g1   = (const float*)d_in[8];
    const float* w_g2   = (const float*)d_in[9];
    const float* b_g2   = (const float*)d_in[10];
    const float* w_fin  = (const float*)d_in[11];
    const float* b_fin  = (const float*)d_in[12];
    float* out = (float*)d_out;

    const int N = in_sizes[0] / DIM;

    __half *resh, *a0h, *a1h, *a2h, *wcat, *wfT;
    cudaGetSymbolAddress((void**)&resh, g_resh);
    cudaGetSymbolAddress((void**)&a0h,  g_a0h);
    cudaGetSymbolAddress((void**)&a1h,  g_a1h);
    cudaGetSymbolAddress((void**)&a2h,  g_a2h);
    cudaGetSymbolAddress((void**)&wcat, g_wcat);
    cudaGetSymbolAddress((void**)&wfT,  g_wfT);

    constexpr int SMEM_CAT   = 2 * (64 * 128 + 320 * 128);   // 96 KB
    constexpr int SMEM_FINAL = 2 * (128 * 128 + 128 * 128);  // 64 KB
    cudaFuncSetAttribute(hgemm_cat,
                         cudaFuncAttributeMaxDynamicSharedMemorySize, SMEM_CAT);
    cudaFuncSetAttribute(hgemm_fin,
                         cudaFuncAttributeMaxDynamicSharedMemorySize, SMEM_FINAL);

    const int gridP  = (N + 7) / 8;

    // 0) weight prep + geometry MLP (one launch)
    prep_geom<<<144 + gridP, 256>>>(w_res, w_init, w_fin, wcat, wfT,
                                    geom, w_g1, b_g1, w_g2, b_g2,
                                    a1h, a2h, N);
    // 1+2) fused: resh (half) + a0h (half) = leaky(X @ [w_res|w_init] + b)
    hgemm_cat<<<dim3((N + 63) / 64, 1), 256, SMEM_CAT>>>(
        X, wcat, b_res, b_init, resh, a0h, N);
    // 3) gather half of LFA1
    gather1<<<(N + 31) / 32, 256>>>(a0h, idx, a1h, N);
    // 4) gather half of LFA2
    gather2<<<(N + 15) / 16, 256>>>(a1h, idx, a2h, N);
    // 5) out = leaky(a2 @ w_fin + b_fin) + resh
    hgemm_fin<<<dim3((N + 127) / 128, 2), 256, SMEM_FINAL>>>(
        a2h, wfT, b_fin, resh, out, N);
}